// round 9
// baseline (speedup 1.0000x reference)
#include <cuda_runtime.h>
#include <cuda_bf16.h>
#include <math.h>
#include <stdint.h>

#define Nc 4096
#define PADCELLS 4356   // 66*66 zero-padded image cells (borders stay zero)

__device__ float g_pp[16777216];
__device__ float g_ao[16777216];

__device__ __nv_bfloat16 g_qkt_hi[33554432], g_qkt_lo[33554432]; // [b][n][1024]
__device__ __nv_bfloat16 g_xt_hi[17842176],  g_xt_lo[17842176];  // [b][cell][512]
__device__ __nv_bfloat16 g_vt_hi[17842176],  g_vt_lo[17842176];
__device__ __nv_bfloat16 g_st_hi[17842176],  g_st_lo[17842176];
__device__ __nv_bfloat16 g_wqk_hi[524288],   g_wqk_lo[524288];
__device__ __nv_bfloat16 g_wv_hi [262144],   g_wv_lo [262144];
__device__ __nv_bfloat16 g_wpr_hi[262144],   g_wpr_lo[262144];
__device__ __nv_bfloat16 g_wpe_hi[2359296],  g_wpe_lo[2359296];  // [tap][o][c]

struct AsyncRes {
    cudaStream_t s1;
    cudaEvent_t eX, eV, eConv;
    AsyncRes() {
        cudaStreamCreateWithFlags(&s1, cudaStreamNonBlocking);
        cudaEventCreateWithFlags(&eX, cudaEventDisableTiming);
        cudaEventCreateWithFlags(&eV, cudaEventDisableTiming);
        cudaEventCreateWithFlags(&eConv, cudaEventDisableTiming);
    }
};
static AsyncRes g_ar;

__device__ __forceinline__ float silu_f(float y) { return y / (1.0f + __expf(-y)); }

__device__ __forceinline__ uint32_t smem_u32(const void* p) {
    uint32_t a;
    asm("{ .reg .u64 t; cvta.to.shared.u64 t, %1; cvt.u32.u64 %0, t; }" : "=r"(a) : "l"(p));
    return a;
}
__device__ __forceinline__ void cp16(uint32_t d, const void* s) {
    asm volatile("cp.async.cg.shared.global [%0], [%1], 16;" :: "r"(d), "l"(s));
}
#define CP_COMMIT() asm volatile("cp.async.commit_group;")
#define LDSM4(r, a) \
    asm volatile("ldmatrix.sync.aligned.m8n8.x4.shared.b16 {%0,%1,%2,%3}, [%4];" \
        : "=r"((r)[0]), "=r"((r)[1]), "=r"((r)[2]), "=r"((r)[3]) : "r"(a))
#define LDSM4T(r, a) \
    asm volatile("ldmatrix.sync.aligned.m8n8.x4.trans.shared.b16 {%0,%1,%2,%3}, [%4];" \
        : "=r"((r)[0]), "=r"((r)[1]), "=r"((r)[2]), "=r"((r)[3]) : "r"(a))
#define MMA16816(d, a, b) \
    asm volatile("mma.sync.aligned.m16n8k16.row.col.f32.bf16.bf16.f32 " \
        "{%0,%1,%2,%3}, {%4,%5,%6,%7}, {%8,%9}, {%0,%1,%2,%3};" \
        : "+f"((d)[0]), "+f"((d)[1]), "+f"((d)[2]), "+f"((d)[3]) \
        : "r"((a)[0]), "r"((a)[1]), "r"((a)[2]), "r"((a)[3]), "r"((b)[0]), "r"((b)[1]))
#define MMA2(d, a, b0, b1) \
    asm volatile("mma.sync.aligned.m16n8k16.row.col.f32.bf16.bf16.f32 " \
        "{%0,%1,%2,%3}, {%4,%5,%6,%7}, {%8,%9}, {%0,%1,%2,%3};" \
        : "+f"((d)[0]), "+f"((d)[1]), "+f"((d)[2]), "+f"((d)[3]) \
        : "r"((a)[0]), "r"((a)[1]), "r"((a)[2]), "r"((a)[3]), "r"(b0), "r"(b1))

__device__ __forceinline__ uint32_t pack_bf16(float lo, float hi) {
    uint32_t r;
    asm("cvt.rn.bf16x2.f32 %0, %1, %2;" : "=r"(r) : "f"(hi), "f"(lo));
    return r;
}

#define ROWB 144
#define TILE_B (128 * ROWB)
#define STAGE_B (2 * TILE_B)
#define SMEM_MMA (2 * STAGE_B)     // 2-stage pipeline: 73,728 B -> 2 CTAs/SM
#define EXPC 0.1803368801f          // 0.125 * log2(e)

// ---------------- prep kernels ----------------
__global__ void split_w(const float* __restrict__ w, __nv_bfloat16* hi, __nv_bfloat16* lo, int n) {
    int i = blockIdx.x * 256 + threadIdx.x;
    if (i < n) {
        float f = w[i];
        __nv_bfloat16 h = __float2bfloat16(f);
        hi[i] = h; lo[i] = __float2bfloat16(f - __bfloat162float(h));
    }
}
__global__ void reorg_pe(const float* __restrict__ pe, __nv_bfloat16* hi, __nv_bfloat16* lo) {
    int i = blockIdx.x * 256 + threadIdx.x;
    if (i < 2359296) {
        int tap = i % 9, c = (i / 9) % 512, o = i / 4608;
        float f = pe[i];
        size_t d = ((size_t)tap * 512 + o) * 512 + c;
        __nv_bfloat16 h = __float2bfloat16(f);
        hi[d] = h; lo[d] = __float2bfloat16(f - __bfloat162float(h));
    }
}
__global__ void transpose_split(const float* __restrict__ X, const float* __restrict__ X2,
                                __nv_bfloat16* __restrict__ hi, __nv_bfloat16* __restrict__ lo)
{
    __shared__ float t[32][33];
    const int tx = threadIdx.x, ty = threadIdx.y;
    const int n0 = blockIdx.x * 32, c0 = blockIdx.y * 32, b = blockIdx.z;
    const float* Xb = X + ((size_t)b * 512 + c0) * Nc + n0;
    const float* X2b = X2 ? (X2 + ((size_t)b * 512 + c0) * Nc + n0) : nullptr;
    for (int i = ty; i < 32; i += 8) {
        float v = Xb[(size_t)i * Nc + tx];
        if (X2b) v += X2b[(size_t)i * Nc + tx];
        t[i][tx] = v;
    }
    __syncthreads();
    for (int i = ty; i < 32; i += 8) {
        float f = t[tx][i];
        int n = n0 + i;
        int cell = ((n >> 6) + 1) * 66 + (n & 63) + 1;
        size_t d = ((size_t)b * PADCELLS + cell) * 512 + c0 + tx;
        __nv_bfloat16 h = __float2bfloat16(f);
        hi[d] = h; lo[d] = __float2bfloat16(f - __bfloat162float(h));
    }
}

// ---------------------------------------------------------------------------
// split-bf16 1x1 GEMM via HMMA, 2-stage cp.async pipeline (2 CTAs/SM).
// mode 0: fp32 [b][O][n]. mode 2: bf16 split [b][n][O]. mode 3: padded image.
// ---------------------------------------------------------------------------
__global__ __launch_bounds__(256, 2) void mma_gemm(
    const __nv_bfloat16* __restrict__ w_hi, const __nv_bfloat16* __restrict__ w_lo,
    const __nv_bfloat16* __restrict__ b_hi, const __nv_bfloat16* __restrict__ b_lo,
    const float* __restrict__ gg, const float* __restrict__ bb,
    const float* __restrict__ rm, const float* __restrict__ rv,
    float* __restrict__ out, int O, int mode,
    __nv_bfloat16* __restrict__ th, __nv_bfloat16* __restrict__ tl)
{
    extern __shared__ char smem[];
    const uint32_t sb = smem_u32(smem);
    const int tid = threadIdx.x;
    const int lane = tid & 31, warp = tid >> 5;
    const int wm = warp >> 2, wn = warp & 3;
    const int n0 = blockIdx.x * 128;
    const int o0 = blockIdx.y * 128;
    const int bz = blockIdx.z;
    const int S = 24;   // 8 c-chunks * 3 split pairs

    auto load_stage = [&](int s) {
        const int c0 = (s / 3) * 64;
        const int p = s % 3;
        const __nv_bfloat16* ap = (p == 1) ? w_lo : w_hi;
        const __nv_bfloat16* bp = (p == 2) ? b_lo : b_hi;
        const uint32_t base = sb + (s & 1) * STAGE_B;
        #pragma unroll
        for (int i = 0; i < 4; i++) {
            int idx = tid + i * 256;
            int row = idx >> 3, kc = idx & 7;
            cp16(base + row * ROWB + kc * 16,
                 ap + (size_t)(o0 + row) * 512 + c0 + kc * 8);
        }
        const size_t bb0 = (size_t)bz * PADCELLS;
        #pragma unroll
        for (int i = 0; i < 4; i++) {
            int idx = tid + i * 256;
            int rn = idx >> 3, kc = idx & 7;
            int nn = n0 + rn;
            int cell = ((nn >> 6) + 1) * 66 + (nn & 63) + 1;
            cp16(base + TILE_B + rn * ROWB + kc * 16,
                 bp + (bb0 + cell) * 512 + c0 + kc * 8);
        }
        CP_COMMIT();
    };

    float acc[4][4][4] = {};

    load_stage(0);
    for (int s = 0; s < S; s++) {
        if (s + 1 < S) { load_stage(s + 1); asm volatile("cp.async.wait_group 1;"); }
        else           { asm volatile("cp.async.wait_group 0;"); }
        __syncthreads();

        const uint32_t base = sb + (s & 1) * STAGE_B;
        const uint32_t aoff = base + (wm * 64 + (lane & 15)) * ROWB + ((lane >> 4) << 4);
        const uint32_t boff = base + TILE_B + (wn * 32 + (lane & 15)) * ROWB + ((lane >> 4) << 4);

        #pragma unroll
        for (int ks = 0; ks < 4; ks++) {
            uint32_t afr[4][4], bfr[4][2], t[4];
            #pragma unroll
            for (int mi = 0; mi < 4; mi++)
                LDSM4(afr[mi], aoff + mi * 16 * ROWB + ks * 32);
            LDSM4(t, boff + ks * 32);
            bfr[0][0] = t[0]; bfr[0][1] = t[2]; bfr[1][0] = t[1]; bfr[1][1] = t[3];
            LDSM4(t, boff + 16 * ROWB + ks * 32);
            bfr[2][0] = t[0]; bfr[2][1] = t[2]; bfr[3][0] = t[1]; bfr[3][1] = t[3];
            #pragma unroll
            for (int mi = 0; mi < 4; mi++)
                #pragma unroll
                for (int ni = 0; ni < 4; ni++)
                    MMA16816(acc[mi][ni], afr[mi], bfr[ni]);
        }
        __syncthreads();
    }

    if (mode == 0) {
        #pragma unroll
        for (int mi = 0; mi < 4; mi++) {
            const int r0 = o0 + wm * 64 + mi * 16 + (lane >> 2);
            const int r1 = r0 + 8;
            const float sc0 = gg[r0] * rsqrtf(rv[r0] + 1e-5f);
            const float sh0 = bb[r0] - rm[r0] * sc0;
            const float sc1 = gg[r1] * rsqrtf(rv[r1] + 1e-5f);
            const float sh1 = bb[r1] - rm[r1] * sc1;
            float* ob0 = out + ((size_t)bz * O + r0) * Nc + n0 + wn * 32 + (lane & 3) * 2;
            float* ob1 = out + ((size_t)bz * O + r1) * Nc + n0 + wn * 32 + (lane & 3) * 2;
            #pragma unroll
            for (int ni = 0; ni < 4; ni++) {
                float2 v0, v1;
                v0.x = silu_f(acc[mi][ni][0] * sc0 + sh0);
                v0.y = silu_f(acc[mi][ni][1] * sc0 + sh0);
                v1.x = silu_f(acc[mi][ni][2] * sc1 + sh1);
                v1.y = silu_f(acc[mi][ni][3] * sc1 + sh1);
                *(float2*)(ob0 + ni * 8) = v0;
                *(float2*)(ob1 + ni * 8) = v1;
            }
        }
    } else {
        __nv_bfloat16* sh = (__nv_bfloat16*)smem;
        __nv_bfloat16* sl = sh + 16384;
        #pragma unroll
        for (int mi = 0; mi < 4; mi++) {
            const int ol0 = wm * 64 + mi * 16 + (lane >> 2);
            const int ol1 = ol0 + 8;
            const int r0 = o0 + ol0, r1 = o0 + ol1;
            const float sc0 = gg[r0] * rsqrtf(rv[r0] + 1e-5f);
            const float sh0 = bb[r0] - rm[r0] * sc0;
            const float sc1 = gg[r1] * rsqrtf(rv[r1] + 1e-5f);
            const float sh1 = bb[r1] - rm[r1] * sc1;
            #pragma unroll
            for (int ni = 0; ni < 4; ni++) {
                const int nl = wn * 32 + ni * 8 + (lane & 3) * 2;
                float v00 = silu_f(acc[mi][ni][0] * sc0 + sh0);
                float v01 = silu_f(acc[mi][ni][1] * sc0 + sh0);
                float v10 = silu_f(acc[mi][ni][2] * sc1 + sh1);
                float v11 = silu_f(acc[mi][ni][3] * sc1 + sh1);
                __nv_bfloat16 h;
                h = __float2bfloat16(v00); sh[nl * 128 + ol0] = h;
                sl[nl * 128 + ol0] = __float2bfloat16(v00 - __bfloat162float(h));
                h = __float2bfloat16(v01); sh[(nl + 1) * 128 + ol0] = h;
                sl[(nl + 1) * 128 + ol0] = __float2bfloat16(v01 - __bfloat162float(h));
                h = __float2bfloat16(v10); sh[nl * 128 + ol1] = h;
                sl[nl * 128 + ol1] = __float2bfloat16(v10 - __bfloat162float(h));
                h = __float2bfloat16(v11); sh[(nl + 1) * 128 + ol1] = h;
                sl[(nl + 1) * 128 + ol1] = __float2bfloat16(v11 - __bfloat162float(h));
            }
        }
        __syncthreads();
        for (int i = tid; i < 2048; i += 256) {
            int n = i >> 4, ch = i & 15;
            uint4 vh4 = *(uint4*)(sh + n * 128 + ch * 8);
            uint4 vl4 = *(uint4*)(sl + n * 128 + ch * 8);
            size_t g;
            if (mode == 2) {
                g = ((size_t)bz * 4096 + n0 + n) * (size_t)O + o0 + ch * 8;
            } else {
                int nn = n0 + n;
                int cell = ((nn >> 6) + 1) * 66 + (nn & 63) + 1;
                g = ((size_t)bz * PADCELLS + cell) * 512 + o0 + ch * 8;
            }
            *(uint4*)(th + g) = vh4;
            *(uint4*)(tl + g) = vl4;
        }
    }
}

// ---------------------------------------------------------------------------
// conv3x3, activation-region reuse + weight-load dedup (18 A-loads/chunk).
// ---------------------------------------------------------------------------
#define CV_REG 38016            // 264 * ROWB
#define CV_A   (2 * CV_REG)     // 76032
#define CV_SMEM (CV_A + 2 * TILE_B)  // 112896
__global__ __launch_bounds__(256, 2) void conv_mma(
    const __nv_bfloat16* __restrict__ w_hi, const __nv_bfloat16* __restrict__ w_lo,
    const __nv_bfloat16* __restrict__ vt_hi, const __nv_bfloat16* __restrict__ vt_lo,
    const float* __restrict__ gg, const float* __restrict__ bb,
    const float* __restrict__ rm, const float* __restrict__ rv,
    float* __restrict__ out)
{
    extern __shared__ char smem[];
    const uint32_t sb = smem_u32(smem);
    const uint32_t regH = sb, regL = sb + CV_REG, aB = sb + CV_A;
    const int tid = threadIdx.x;
    const int lane = tid & 31, warp = tid >> 5;
    const int wm = warp >> 2, wn = warp & 3;
    const int n0 = blockIdx.x * 128, h0 = blockIdx.x * 2;
    const int o0 = blockIdx.y * 128;
    const int bz = blockIdx.z;
    const size_t bb0 = (size_t)bz * PADCELLS;

    const int nA = wn * 32 + (lane & 15);
    const int gA = (nA >> 6) * 66 + (nA & 63);
    const int nB = nA + 16;
    const int gB = (nB >> 6) * 66 + (nB & 63);

    float acc[4][4][4] = {};

    for (int cc = 0; cc < 8; cc++) {
        const int c0 = cc * 64;
        __syncthreads();   // previous chunk fully consumed region + A buffers

        // region load (hi+lo): 264 rows x 64ch
        for (int i = tid; i < 2112; i += 256) {
            int rr = i >> 3, c = i & 7;
            size_t src = (bb0 + h0 * 66 + rr) * 512 + c0 + c * 8;
            cp16(regH + rr * ROWB + c * 16, vt_hi + src);
            cp16(regL + rr * ROWB + c * 16, vt_lo + src);
        }
        // A load li: tap = li/2, hi if even else lo, into buffer li&1
        auto loadA = [&](int li) {
            const int tap = li >> 1;
            const __nv_bfloat16* ap = ((li & 1) ? w_lo : w_hi) + (size_t)tap * 262144;
            const uint32_t buf = aB + (li & 1) * TILE_B;
            #pragma unroll
            for (int i = 0; i < 4; i++) {
                int idx = tid + i * 256;
                int row = idx >> 3, kc = idx & 7;
                cp16(buf + row * ROWB + kc * 16,
                     ap + (size_t)(o0 + row) * 512 + c0 + kc * 8);
            }
            CP_COMMIT();
        };
        loadA(0);   // group 0 = region + A0
        loadA(1);   // group 1 = A1

        for (int li = 0; li < 18; li++) {
            if (li < 17) asm volatile("cp.async.wait_group 1;");
            else         asm volatile("cp.async.wait_group 0;");
            __syncthreads();

            const int tap = li >> 1;
            const int toff = (tap / 3) * 66 + (tap % 3);
            const uint32_t abuf = aB + (li & 1) * TILE_B;
            const uint32_t aoff = abuf + (wm * 64 + (lane & 15)) * ROWB + ((lane >> 4) << 4);

            auto mma_pass = [&](uint32_t reg) {
                const uint32_t boffA = reg + (gA + toff) * ROWB + ((lane >> 4) << 4);
                const uint32_t boffB = reg + (gB + toff) * ROWB + ((lane >> 4) << 4);
                #pragma unroll
                for (int ks = 0; ks < 4; ks++) {
                    uint32_t afr[4][4], bfr[4][2], t4[4];
                    #pragma unroll
                    for (int mi = 0; mi < 4; mi++)
                        LDSM4(afr[mi], aoff + mi * 16 * ROWB + ks * 32);
                    LDSM4(t4, boffA + ks * 32);
                    bfr[0][0] = t4[0]; bfr[0][1] = t4[2]; bfr[1][0] = t4[1]; bfr[1][1] = t4[3];
                    LDSM4(t4, boffB + ks * 32);
                    bfr[2][0] = t4[0]; bfr[2][1] = t4[2]; bfr[3][0] = t4[1]; bfr[3][1] = t4[3];
                    #pragma unroll
                    for (int mi = 0; mi < 4; mi++)
                        #pragma unroll
                        for (int ni = 0; ni < 4; ni++)
                            MMA16816(acc[mi][ni], afr[mi], bfr[ni]);
                }
            };
            if (li & 1) {               // w_lo: one pass over regH
                mma_pass(regH);
            } else {                    // w_hi: regH and regL
                mma_pass(regH);
                mma_pass(regL);
            }
            __syncthreads();
            if (li + 2 < 18) loadA(li + 2);   // overwrite just-consumed buffer
        }
    }

    // BN + SiLU fp32 epilogue
    #pragma unroll
    for (int mi = 0; mi < 4; mi++) {
        const int r0 = o0 + wm * 64 + mi * 16 + (lane >> 2);
        const int r1 = r0 + 8;
        const float sc0 = gg[r0] * rsqrtf(rv[r0] + 1e-5f);
        const float sh0 = bb[r0] - rm[r0] * sc0;
        const float sc1 = gg[r1] * rsqrtf(rv[r1] + 1e-5f);
        const float sh1 = bb[r1] - rm[r1] * sc1;
        float* ob0 = out + ((size_t)bz * 512 + r0) * Nc + n0 + wn * 32 + (lane & 3) * 2;
        float* ob1 = out + ((size_t)bz * 512 + r1) * Nc + n0 + wn * 32 + (lane & 3) * 2;
        #pragma unroll
        for (int ni = 0; ni < 4; ni++) {
            float2 v0, v1;
            v0.x = silu_f(acc[mi][ni][0] * sc0 + sh0);
            v0.y = silu_f(acc[mi][ni][1] * sc0 + sh0);
            v1.x = silu_f(acc[mi][ni][2] * sc1 + sh1);
            v1.y = silu_f(acc[mi][ni][3] * sc1 + sh1);
            *(float2*)(ob0 + ni * 8) = v0;
            *(float2*)(ob1 + ni * 8) = v1;
        }
    }
}

// ---------------------------------------------------------------------------
// HMMA flash attention, warp-local softmax; Q fragments cached in registers.
// S = QhKh + QlKh + QhKl ; O = PhVh + PhVl.
// ---------------------------------------------------------------------------
#define AT_SMEM 110592
__global__ __launch_bounds__(256, 1) void attn_mma(
    const __nv_bfloat16* __restrict__ qh_, const __nv_bfloat16* __restrict__ ql_,
    const __nv_bfloat16* __restrict__ vh_, const __nv_bfloat16* __restrict__ vl_,
    float* __restrict__ ao)
{
    extern __shared__ char smem[];
    const uint32_t sb = smem_u32(smem);
    const uint32_t sQh = sb, sQl = sb + 18432;
    const uint32_t sKV = sb + 36864;
    float* Osf = (float*)(smem + 36864);   // [64][132] overlay after loop

    const int tid = threadIdx.x, lane = tid & 31, warp = tid >> 5;
    const int bh = blockIdx.y;
    const int head = bh & 7, ba = bh >> 3;
    const int b = ba >> 2, area = ba & 3;
    const int q0 = blockIdx.x * 128;
    const int nb = area * 1024;

    const size_t qrow0 = ((size_t)b * 4096 + nb + q0) * 1024 + head * 64;
    const size_t krow0 = ((size_t)b * 4096 + nb) * 1024 + 512 + head * 64;
    const size_t vbase = (size_t)b * PADCELLS * 512 + head * 64;
    const int imrow0 = nb / 64;

    auto loadKV = [&](int t) {
        const uint32_t kb = sKV + (t & 1) * 36864;
        const size_t kr = krow0 + (size_t)(t * 64) * 1024;
        for (int i = tid; i < 512; i += 256) {
            int r = i >> 3, c = i & 7;
            cp16(kb + r * ROWB + c * 16,        qh_ + kr + (size_t)r * 1024 + c * 8);
            cp16(kb + 9216 + r * ROWB + c * 16, ql_ + kr + (size_t)r * 1024 + c * 8);
            size_t vr = vbase + (size_t)((imrow0 + t + 1) * 66 + r + 1) * 512;
            cp16(kb + 18432 + r * ROWB + c * 16, vh_ + vr + c * 8);
            cp16(kb + 27648 + r * ROWB + c * 16, vl_ + vr + c * 8);
        }
        CP_COMMIT();
    };

    for (int i = tid; i < 1024; i += 256) {
        int r = i >> 3, c = i & 7;
        cp16(sQh + r * ROWB + c * 16, qh_ + qrow0 + (size_t)r * 1024 + c * 8);
        cp16(sQl + r * ROWB + c * 16, ql_ + qrow0 + (size_t)r * 1024 + c * 8);
    }
    loadKV(0);   // commit includes Q loads
    loadKV(1);

    float oacc[8][4] = {};
    float mrun0 = -1e30f, mrun1 = -1e30f, lrun0 = 0.0f, lrun1 = 0.0f;
    uint32_t qhf[4][4], qlf[4][4];

    for (int kt = 0; kt < 16; kt++) {
        if (kt < 15) asm volatile("cp.async.wait_group 1;");
        else         asm volatile("cp.async.wait_group 0;");
        __syncthreads();

        if (kt == 0) {
            #pragma unroll
            for (int ks = 0; ks < 4; ks++) {
                const uint32_t colb = ((lane >> 4) << 4) + ks * 32;
                const uint32_t qoff = (warp * 16 + (lane & 15)) * ROWB + colb;
                LDSM4(qhf[ks], sQh + qoff);
                LDSM4(qlf[ks], sQl + qoff);
            }
        }

        const uint32_t kb = sKV + (kt & 1) * 36864;

        // ---- S (raw scores): 16 q-rows x 64 keys per warp ----
        float sa[8][4] = {};
        #pragma unroll
        for (int ks = 0; ks < 4; ks++) {
            const uint32_t colb = ((lane >> 4) << 4) + ks * 32;
            uint32_t t4[4];
            uint32_t bh2[8][2], bl2[8][2];
            #pragma unroll
            for (int nbk = 0; nbk < 4; nbk++) {
                const uint32_t koff = (nbk * 16 + (lane & 15)) * ROWB + colb;
                LDSM4(t4, kb + koff);
                bh2[2*nbk][0] = t4[0]; bh2[2*nbk][1] = t4[2];
                bh2[2*nbk+1][0] = t4[1]; bh2[2*nbk+1][1] = t4[3];
                LDSM4(t4, kb + 9216 + koff);
                bl2[2*nbk][0] = t4[0]; bl2[2*nbk][1] = t4[2];
                bl2[2*nbk+1][0] = t4[1]; bl2[2*nbk+1][1] = t4[3];
            }
            #pragma unroll
            for (int ni = 0; ni < 8; ni++) {
                MMA16816(sa[ni], qhf[ks], bh2[ni]);
                MMA16816(sa[ni], qlf[ks], bh2[ni]);
                MMA16816(sa[ni], qhf[ks], bl2[ni]);
            }
        }

        // ---- warp-local online softmax ----
        float m0 = -1e30f, m1 = -1e30f;
        #pragma unroll
        for (int ni = 0; ni < 8; ni++) {
            m0 = fmaxf(m0, fmaxf(sa[ni][0], sa[ni][1]));
            m1 = fmaxf(m1, fmaxf(sa[ni][2], sa[ni][3]));
        }
        m0 = fmaxf(m0, __shfl_xor_sync(0xffffffff, m0, 1));
        m0 = fmaxf(m0, __shfl_xor_sync(0xffffffff, m0, 2));
        m1 = fmaxf(m1, __shfl_xor_sync(0xffffffff, m1, 1));
        m1 = fmaxf(m1, __shfl_xor_sync(0xffffffff, m1, 2));
        const float mn0 = fmaxf(mrun0, m0), mn1 = fmaxf(mrun1, m1);
        const float f0 = exp2f((mrun0 - mn0) * EXPC);
        const float f1 = exp2f((mrun1 - mn1) * EXPC);
        mrun0 = mn0; mrun1 = mn1;

        float s0 = 0.0f, s1 = 0.0f;
        #pragma unroll
        for (int ni = 0; ni < 8; ni++) {
            sa[ni][0] = exp2f((sa[ni][0] - mn0) * EXPC);
            sa[ni][1] = exp2f((sa[ni][1] - mn0) * EXPC);
            sa[ni][2] = exp2f((sa[ni][2] - mn1) * EXPC);
            sa[ni][3] = exp2f((sa[ni][3] - mn1) * EXPC);
            s0 += sa[ni][0] + sa[ni][1];
            s1 += sa[ni][2] + sa[ni][3];
        }
        s0 += __shfl_xor_sync(0xffffffff, s0, 1);
        s0 += __shfl_xor_sync(0xffffffff, s0, 2);
        s1 += __shfl_xor_sync(0xffffffff, s1, 1);
        s1 += __shfl_xor_sync(0xffffffff, s1, 2);
        lrun0 = lrun0 * f0 + s0;
        lrun1 = lrun1 * f1 + s1;
        #pragma unroll
        for (int ni = 0; ni < 8; ni++) {
            oacc[ni][0] *= f0; oacc[ni][1] *= f0;
            oacc[ni][2] *= f1; oacc[ni][3] *= f1;
        }

        // ---- O += Ph*Vh + Ph*Vl ----
        #pragma unroll
        for (int kf = 0; kf < 4; kf++) {
            uint32_t ah[4];
            ah[0] = pack_bf16(sa[2*kf][0],   sa[2*kf][1]);
            ah[1] = pack_bf16(sa[2*kf][2],   sa[2*kf][3]);
            ah[2] = pack_bf16(sa[2*kf+1][0], sa[2*kf+1][1]);
            ah[3] = pack_bf16(sa[2*kf+1][2], sa[2*kf+1][3]);
            uint32_t vh2[8][2], vl2[8][2], t4[4];
            #pragma unroll
            for (int dsp = 0; dsp < 4; dsp++) {
                const uint32_t voff = (kf * 16 + (lane & 15)) * ROWB
                                    + dsp * 32 + ((lane >> 4) << 4);
                LDSM4T(t4, kb + 18432 + voff);
                vh2[dsp*2][0] = t4[0]; vh2[dsp*2][1] = t4[1];
                vh2[dsp*2+1][0] = t4[2]; vh2[dsp*2+1][1] = t4[3];
                LDSM4T(t4, kb + 27648 + voff);
                vl2[dsp*2][0] = t4[0]; vl2[dsp*2][1] = t4[1];
                vl2[dsp*2+1][0] = t4[2]; vl2[dsp*2+1][1] = t4[3];
            }
            #pragma unroll
            for (int ni = 0; ni < 8; ni++) {
                MMA2(oacc[ni], ah, vh2[ni][0], vh2[ni][1]);
                MMA2(oacc[ni], ah, vl2[ni][0], vl2[ni][1]);
            }
        }
        __syncthreads();
        if (kt + 2 < 16) loadKV(kt + 2);
    }
    __syncthreads();

    // ---- normalize in registers, stage [d][q], coalesced store ----
    const float inv0 = 1.0f / lrun0, inv1 = 1.0f / lrun1;
    const int r = warp * 16 + (lane >> 2);
    #pragma unroll
    for (int ni = 0; ni < 8; ni++) {
        int d = ni * 8 + (lane & 3) * 2;
        Osf[d * 132 + r]           = oacc[ni][0] * inv0;
        Osf[(d + 1) * 132 + r]     = oacc[ni][1] * inv0;
        Osf[d * 132 + r + 8]       = oacc[ni][2] * inv1;
        Osf[(d + 1) * 132 + r + 8] = oacc[ni][3] * inv1;
    }
    __syncthreads();
    float* og = ao + ((size_t)b * 512 + head * 64) * Nc + nb + q0;
    for (int i = tid; i < 8192; i += 256) {
        int d = i >> 7, q = i & 127;
        og[(size_t)d * Nc + q] = Osf[d * 132 + q];
    }
}

// ---------------------------------------------------------------------------
extern "C" void kernel_launch(void* const* d_in, const int* in_sizes, int n_in,
                              void* d_out, int out_size)
{
    const float* x     = (const float*)d_in[0];
    const float* qk_w  = (const float*)d_in[1];
    const float* qk_g  = (const float*)d_in[2];
    const float* qk_b  = (const float*)d_in[3];
    const float* qk_rm = (const float*)d_in[4];
    const float* qk_rv = (const float*)d_in[5];
    const float* v_w   = (const float*)d_in[6];
    const float* v_g   = (const float*)d_in[7];
    const float* v_b   = (const float*)d_in[8];
    const float* v_rm  = (const float*)d_in[9];
    const float* v_rv  = (const float*)d_in[10];
    const float* pe_w  = (const float*)d_in[11];
    const float* pe_g  = (const float*)d_in[12];
    const float* pe_b  = (const float*)d_in[13];
    const float* pe_rm = (const float*)d_in[14];
    const float* pe_rv = (const float*)d_in[15];
    const float* pr_w  = (const float*)d_in[16];
    const float* pr_g  = (const float*)d_in[17];
    const float* pr_b  = (const float*)d_in[18];
    const float* pr_rm = (const float*)d_in[19];
    const float* pr_rv = (const float*)d_in[20];

    float *ppb, *aob;
    cudaGetSymbolAddress((void**)&ppb, g_pp);
    cudaGetSymbolAddress((void**)&aob, g_ao);
    __nv_bfloat16 *qkth, *qktl, *xth, *xtl, *vth, *vtl, *sth, *stl;
    __nv_bfloat16 *wqh, *wql, *wvh, *wvl, *wph, *wpl, *weh, *wel;
    cudaGetSymbolAddress((void**)&qkth, g_qkt_hi); cudaGetSymbolAddress((void**)&qktl, g_qkt_lo);
    cudaGetSymbolAddress((void**)&xth, g_xt_hi); cudaGetSymbolAddress((void**)&xtl, g_xt_lo);
    cudaGetSymbolAddress((void**)&vth, g_vt_hi); cudaGetSymbolAddress((void**)&vtl, g_vt_lo);
    cudaGetSymbolAddress((void**)&sth, g_st_hi); cudaGetSymbolAddress((void**)&stl, g_st_lo);
    cudaGetSymbolAddress((void**)&wqh, g_wqk_hi); cudaGetSymbolAddress((void**)&wql, g_wqk_lo);
    cudaGetSymbolAddress((void**)&wvh, g_wv_hi);  cudaGetSymbolAddress((void**)&wvl, g_wv_lo);
    cudaGetSymbolAddress((void**)&wph, g_wpr_hi); cudaGetSymbolAddress((void**)&wpl, g_wpr_lo);
    cudaGetSymbolAddress((void**)&weh, g_wpe_hi); cudaGetSymbolAddress((void**)&wel, g_wpe_lo);

    cudaFuncSetAttribute(mma_gemm, cudaFuncAttributeMaxDynamicSharedMemorySize, SMEM_MMA);
    cudaFuncSetAttribute(conv_mma, cudaFuncAttributeMaxDynamicSharedMemorySize, CV_SMEM);
    cudaFuncSetAttribute(attn_mma, cudaFuncAttributeMaxDynamicSharedMemorySize, AT_SMEM);

    cudaStream_t s0 = 0, s1 = g_ar.s1;

    // ---- s0: x transpose -> qk GEMM -> attn ----
    transpose_split<<<dim3(128, 16, 8), dim3(32, 8), 0, s0>>>(x, nullptr, xth, xtl);
    cudaEventRecord(g_ar.eX, s0);
    split_w<<<2048, 256, 0, s0>>>(qk_w, wqh, wql, 524288);
    mma_gemm<<<dim3(32, 8, 8), 256, SMEM_MMA, s0>>>(wqh, wql, xth, xtl,
        qk_g, qk_b, qk_rm, qk_rv, nullptr, 1024, 2, qkth, qktl);

    // ---- s1: preps -> v GEMM -> conv ----
    reorg_pe<<<9216, 256, 0, s1>>>(pe_w, weh, wel);
    split_w<<<1024, 256, 0, s1>>>(v_w,  wvh, wvl, 262144);
    split_w<<<1024, 256, 0, s1>>>(pr_w, wph, wpl, 262144);
    cudaStreamWaitEvent(s1, g_ar.eX, 0);
    mma_gemm<<<dim3(32, 4, 8), 256, SMEM_MMA, s1>>>(wvh, wvl, xth, xtl,
        v_g, v_b, v_rm, v_rv, nullptr, 512, 3, vth, vtl);
    cudaEventRecord(g_ar.eV, s1);
    conv_mma<<<dim3(32, 4, 8), 256, CV_SMEM, s1>>>(weh, wel, vth, vtl,
        pe_g, pe_b, pe_rm, pe_rv, ppb);
    cudaEventRecord(g_ar.eConv, s1);

    // ---- s0: attention ----
    cudaStreamWaitEvent(s0, g_ar.eV, 0);
    attn_mma<<<dim3(8, 256), 256, AT_SMEM, s0>>>(qkth, qktl, vth, vtl, aob);

    // ---- join, final GEMM ----
    cudaStreamWaitEvent(s0, g_ar.eConv, 0);
    transpose_split<<<dim3(128, 16, 8), dim3(32, 8), 0, s0>>>(aob, ppb, sth, stl);
    mma_gemm<<<dim3(32, 4, 8), 256, SMEM_MMA, s0>>>(wph, wpl, sth, stl,
        pr_g, pr_b, pr_rm, pr_rv, (float*)d_out, 512, 0, nullptr, nullptr);
}

// round 10
// speedup vs baseline: 1.0439x; 1.0439x over previous
#include <cuda_runtime.h>
#include <cuda_bf16.h>
#include <math.h>
#include <stdint.h>

#define Nc 4096
#define PADCELLS 4356   // 66*66 zero-padded image cells (borders stay zero)

__device__ float g_pp[16777216];
__device__ float g_ao[16777216];

__device__ __nv_bfloat16 g_qkt_hi[33554432], g_qkt_lo[33554432]; // [b][n][1024]
__device__ __nv_bfloat16 g_xt_hi[17842176],  g_xt_lo[17842176];  // [b][cell][512]
__device__ __nv_bfloat16 g_vt_hi[17842176],  g_vt_lo[17842176];
__device__ __nv_bfloat16 g_st_hi[17842176],  g_st_lo[17842176];
__device__ __nv_bfloat16 g_wqk_hi[524288],   g_wqk_lo[524288];
__device__ __nv_bfloat16 g_wv_hi [262144],   g_wv_lo [262144];
__device__ __nv_bfloat16 g_wpr_hi[262144],   g_wpr_lo[262144];
__device__ __nv_bfloat16 g_wpe_hi[2359296],  g_wpe_lo[2359296];  // [tap][o][c]

struct AsyncRes {
    cudaStream_t s1;
    cudaEvent_t eX, eV, eConv;
    AsyncRes() {
        cudaStreamCreateWithFlags(&s1, cudaStreamNonBlocking);
        cudaEventCreateWithFlags(&eX, cudaEventDisableTiming);
        cudaEventCreateWithFlags(&eV, cudaEventDisableTiming);
        cudaEventCreateWithFlags(&eConv, cudaEventDisableTiming);
    }
};
static AsyncRes g_ar;

__device__ __forceinline__ float silu_f(float y) { return y / (1.0f + __expf(-y)); }

__device__ __forceinline__ uint32_t smem_u32(const void* p) {
    uint32_t a;
    asm("{ .reg .u64 t; cvta.to.shared.u64 t, %1; cvt.u32.u64 %0, t; }" : "=r"(a) : "l"(p));
    return a;
}
__device__ __forceinline__ void cp16(uint32_t d, const void* s) {
    asm volatile("cp.async.cg.shared.global [%0], [%1], 16;" :: "r"(d), "l"(s));
}
#define CP_COMMIT() asm volatile("cp.async.commit_group;")
#define LDSM4(r, a) \
    asm volatile("ldmatrix.sync.aligned.m8n8.x4.shared.b16 {%0,%1,%2,%3}, [%4];" \
        : "=r"((r)[0]), "=r"((r)[1]), "=r"((r)[2]), "=r"((r)[3]) : "r"(a))
#define LDSM4T(r, a) \
    asm volatile("ldmatrix.sync.aligned.m8n8.x4.trans.shared.b16 {%0,%1,%2,%3}, [%4];" \
        : "=r"((r)[0]), "=r"((r)[1]), "=r"((r)[2]), "=r"((r)[3]) : "r"(a))
#define MMA16816(d, a, b) \
    asm volatile("mma.sync.aligned.m16n8k16.row.col.f32.bf16.bf16.f32 " \
        "{%0,%1,%2,%3}, {%4,%5,%6,%7}, {%8,%9}, {%0,%1,%2,%3};" \
        : "+f"((d)[0]), "+f"((d)[1]), "+f"((d)[2]), "+f"((d)[3]) \
        : "r"((a)[0]), "r"((a)[1]), "r"((a)[2]), "r"((a)[3]), "r"((b)[0]), "r"((b)[1]))
#define MMA2(d, a, b0, b1) \
    asm volatile("mma.sync.aligned.m16n8k16.row.col.f32.bf16.bf16.f32 " \
        "{%0,%1,%2,%3}, {%4,%5,%6,%7}, {%8,%9}, {%0,%1,%2,%3};" \
        : "+f"((d)[0]), "+f"((d)[1]), "+f"((d)[2]), "+f"((d)[3]) \
        : "r"((a)[0]), "r"((a)[1]), "r"((a)[2]), "r"((a)[3]), "r"(b0), "r"(b1))

__device__ __forceinline__ uint32_t pack_bf16(float lo, float hi) {
    uint32_t r;
    asm("cvt.rn.bf16x2.f32 %0, %1, %2;" : "=r"(r) : "f"(hi), "f"(lo));
    return r;
}

#define ROWB 144
#define TILE_B (128 * ROWB)
#define STAGE_B (2 * TILE_B)
#define SMEM_MMA (2 * STAGE_B)     // 2-stage pipeline: 73,728 B -> 2 CTAs/SM
#define EXPC 0.1803368801f          // 0.125 * log2(e)

// ---------------- prep kernels ----------------
__global__ void split_w(const float* __restrict__ w, __nv_bfloat16* hi, __nv_bfloat16* lo, int n) {
    int i = blockIdx.x * 256 + threadIdx.x;
    if (i < n) {
        float f = w[i];
        __nv_bfloat16 h = __float2bfloat16(f);
        hi[i] = h; lo[i] = __float2bfloat16(f - __bfloat162float(h));
    }
}
__global__ void reorg_pe(const float* __restrict__ pe, __nv_bfloat16* hi, __nv_bfloat16* lo) {
    int i = blockIdx.x * 256 + threadIdx.x;
    if (i < 2359296) {
        int tap = i % 9, c = (i / 9) % 512, o = i / 4608;
        float f = pe[i];
        size_t d = ((size_t)tap * 512 + o) * 512 + c;
        __nv_bfloat16 h = __float2bfloat16(f);
        hi[d] = h; lo[d] = __float2bfloat16(f - __bfloat162float(h));
    }
}
__global__ void transpose_split(const float* __restrict__ X, const float* __restrict__ X2,
                                __nv_bfloat16* __restrict__ hi, __nv_bfloat16* __restrict__ lo)
{
    __shared__ float t[32][33];
    const int tx = threadIdx.x, ty = threadIdx.y;
    const int n0 = blockIdx.x * 32, c0 = blockIdx.y * 32, b = blockIdx.z;
    const float* Xb = X + ((size_t)b * 512 + c0) * Nc + n0;
    const float* X2b = X2 ? (X2 + ((size_t)b * 512 + c0) * Nc + n0) : nullptr;
    for (int i = ty; i < 32; i += 8) {
        float v = Xb[(size_t)i * Nc + tx];
        if (X2b) v += X2b[(size_t)i * Nc + tx];
        t[i][tx] = v;
    }
    __syncthreads();
    for (int i = ty; i < 32; i += 8) {
        float f = t[tx][i];
        int n = n0 + i;
        int cell = ((n >> 6) + 1) * 66 + (n & 63) + 1;
        size_t d = ((size_t)b * PADCELLS + cell) * 512 + c0 + tx;
        __nv_bfloat16 h = __float2bfloat16(f);
        hi[d] = h; lo[d] = __float2bfloat16(f - __bfloat162float(h));
    }
}

// ---------------------------------------------------------------------------
// split-bf16 1x1 GEMM via HMMA, 2-stage cp.async pipeline (2 CTAs/SM).
// mode 0: fp32 [b][O][n]. mode 2: bf16 split [b][n][O]. mode 3: padded image.
// ---------------------------------------------------------------------------
__global__ __launch_bounds__(256, 2) void mma_gemm(
    const __nv_bfloat16* __restrict__ w_hi, const __nv_bfloat16* __restrict__ w_lo,
    const __nv_bfloat16* __restrict__ b_hi, const __nv_bfloat16* __restrict__ b_lo,
    const float* __restrict__ gg, const float* __restrict__ bb,
    const float* __restrict__ rm, const float* __restrict__ rv,
    float* __restrict__ out, int O, int mode,
    __nv_bfloat16* __restrict__ th, __nv_bfloat16* __restrict__ tl)
{
    extern __shared__ char smem[];
    const uint32_t sb = smem_u32(smem);
    const int tid = threadIdx.x;
    const int lane = tid & 31, warp = tid >> 5;
    const int wm = warp >> 2, wn = warp & 3;
    const int n0 = blockIdx.x * 128;
    const int o0 = blockIdx.y * 128;
    const int bz = blockIdx.z;
    const int S = 24;   // 8 c-chunks * 3 split pairs

    auto load_stage = [&](int s) {
        const int c0 = (s / 3) * 64;
        const int p = s % 3;
        const __nv_bfloat16* ap = (p == 1) ? w_lo : w_hi;
        const __nv_bfloat16* bp = (p == 2) ? b_lo : b_hi;
        const uint32_t base = sb + (s & 1) * STAGE_B;
        #pragma unroll
        for (int i = 0; i < 4; i++) {
            int idx = tid + i * 256;
            int row = idx >> 3, kc = idx & 7;
            cp16(base + row * ROWB + kc * 16,
                 ap + (size_t)(o0 + row) * 512 + c0 + kc * 8);
        }
        const size_t bb0 = (size_t)bz * PADCELLS;
        #pragma unroll
        for (int i = 0; i < 4; i++) {
            int idx = tid + i * 256;
            int rn = idx >> 3, kc = idx & 7;
            int nn = n0 + rn;
            int cell = ((nn >> 6) + 1) * 66 + (nn & 63) + 1;
            cp16(base + TILE_B + rn * ROWB + kc * 16,
                 bp + (bb0 + cell) * 512 + c0 + kc * 8);
        }
        CP_COMMIT();
    };

    float acc[4][4][4] = {};

    load_stage(0);
    for (int s = 0; s < S; s++) {
        if (s + 1 < S) { load_stage(s + 1); asm volatile("cp.async.wait_group 1;"); }
        else           { asm volatile("cp.async.wait_group 0;"); }
        __syncthreads();

        const uint32_t base = sb + (s & 1) * STAGE_B;
        const uint32_t aoff = base + (wm * 64 + (lane & 15)) * ROWB + ((lane >> 4) << 4);
        const uint32_t boff = base + TILE_B + (wn * 32 + (lane & 15)) * ROWB + ((lane >> 4) << 4);

        #pragma unroll
        for (int ks = 0; ks < 4; ks++) {
            uint32_t afr[4][4], bfr[4][2], t[4];
            #pragma unroll
            for (int mi = 0; mi < 4; mi++)
                LDSM4(afr[mi], aoff + mi * 16 * ROWB + ks * 32);
            LDSM4(t, boff + ks * 32);
            bfr[0][0] = t[0]; bfr[0][1] = t[2]; bfr[1][0] = t[1]; bfr[1][1] = t[3];
            LDSM4(t, boff + 16 * ROWB + ks * 32);
            bfr[2][0] = t[0]; bfr[2][1] = t[2]; bfr[3][0] = t[1]; bfr[3][1] = t[3];
            #pragma unroll
            for (int mi = 0; mi < 4; mi++)
                #pragma unroll
                for (int ni = 0; ni < 4; ni++)
                    MMA16816(acc[mi][ni], afr[mi], bfr[ni]);
        }
        __syncthreads();
    }

    if (mode == 0) {
        #pragma unroll
        for (int mi = 0; mi < 4; mi++) {
            const int r0 = o0 + wm * 64 + mi * 16 + (lane >> 2);
            const int r1 = r0 + 8;
            const float sc0 = gg[r0] * rsqrtf(rv[r0] + 1e-5f);
            const float sh0 = bb[r0] - rm[r0] * sc0;
            const float sc1 = gg[r1] * rsqrtf(rv[r1] + 1e-5f);
            const float sh1 = bb[r1] - rm[r1] * sc1;
            float* ob0 = out + ((size_t)bz * O + r0) * Nc + n0 + wn * 32 + (lane & 3) * 2;
            float* ob1 = out + ((size_t)bz * O + r1) * Nc + n0 + wn * 32 + (lane & 3) * 2;
            #pragma unroll
            for (int ni = 0; ni < 4; ni++) {
                float2 v0, v1;
                v0.x = silu_f(acc[mi][ni][0] * sc0 + sh0);
                v0.y = silu_f(acc[mi][ni][1] * sc0 + sh0);
                v1.x = silu_f(acc[mi][ni][2] * sc1 + sh1);
                v1.y = silu_f(acc[mi][ni][3] * sc1 + sh1);
                *(float2*)(ob0 + ni * 8) = v0;
                *(float2*)(ob1 + ni * 8) = v1;
            }
        }
    } else {
        __nv_bfloat16* sh = (__nv_bfloat16*)smem;
        __nv_bfloat16* sl = sh + 16384;
        #pragma unroll
        for (int mi = 0; mi < 4; mi++) {
            const int ol0 = wm * 64 + mi * 16 + (lane >> 2);
            const int ol1 = ol0 + 8;
            const int r0 = o0 + ol0, r1 = o0 + ol1;
            const float sc0 = gg[r0] * rsqrtf(rv[r0] + 1e-5f);
            const float sh0 = bb[r0] - rm[r0] * sc0;
            const float sc1 = gg[r1] * rsqrtf(rv[r1] + 1e-5f);
            const float sh1 = bb[r1] - rm[r1] * sc1;
            #pragma unroll
            for (int ni = 0; ni < 4; ni++) {
                const int nl = wn * 32 + ni * 8 + (lane & 3) * 2;
                float v00 = silu_f(acc[mi][ni][0] * sc0 + sh0);
                float v01 = silu_f(acc[mi][ni][1] * sc0 + sh0);
                float v10 = silu_f(acc[mi][ni][2] * sc1 + sh1);
                float v11 = silu_f(acc[mi][ni][3] * sc1 + sh1);
                __nv_bfloat16 h;
                h = __float2bfloat16(v00); sh[nl * 128 + ol0] = h;
                sl[nl * 128 + ol0] = __float2bfloat16(v00 - __bfloat162float(h));
                h = __float2bfloat16(v01); sh[(nl + 1) * 128 + ol0] = h;
                sl[(nl + 1) * 128 + ol0] = __float2bfloat16(v01 - __bfloat162float(h));
                h = __float2bfloat16(v10); sh[nl * 128 + ol1] = h;
                sl[nl * 128 + ol1] = __float2bfloat16(v10 - __bfloat162float(h));
                h = __float2bfloat16(v11); sh[(nl + 1) * 128 + ol1] = h;
                sl[(nl + 1) * 128 + ol1] = __float2bfloat16(v11 - __bfloat162float(h));
            }
        }
        __syncthreads();
        for (int i = tid; i < 2048; i += 256) {
            int n = i >> 4, ch = i & 15;
            uint4 vh4 = *(uint4*)(sh + n * 128 + ch * 8);
            uint4 vl4 = *(uint4*)(sl + n * 128 + ch * 8);
            size_t g;
            if (mode == 2) {
                g = ((size_t)bz * 4096 + n0 + n) * (size_t)O + o0 + ch * 8;
            } else {
                int nn = n0 + n;
                int cell = ((nn >> 6) + 1) * 66 + (nn & 63) + 1;
                g = ((size_t)bz * PADCELLS + cell) * 512 + o0 + ch * 8;
            }
            *(uint4*)(th + g) = vh4;
            *(uint4*)(tl + g) = vl4;
        }
    }
}

// ---------------------------------------------------------------------------
// conv3x3, activation-region reuse + weight-load dedup (18 A-loads/chunk):
// li even -> w_hi[tap]: mma over regH then regL; li odd -> w_lo[tap]: regH only.
// ---------------------------------------------------------------------------
#define CV_REG 38016            // 264 * ROWB
#define CV_A   (2 * CV_REG)     // 76032
#define CV_SMEM (CV_A + 2 * TILE_B)  // 112896
__global__ __launch_bounds__(256, 2) void conv_mma(
    const __nv_bfloat16* __restrict__ w_hi, const __nv_bfloat16* __restrict__ w_lo,
    const __nv_bfloat16* __restrict__ vt_hi, const __nv_bfloat16* __restrict__ vt_lo,
    const float* __restrict__ gg, const float* __restrict__ bb,
    const float* __restrict__ rm, const float* __restrict__ rv,
    float* __restrict__ out)
{
    extern __shared__ char smem[];
    const uint32_t sb = smem_u32(smem);
    const uint32_t regH = sb, regL = sb + CV_REG, aB = sb + CV_A;
    const int tid = threadIdx.x;
    const int lane = tid & 31, warp = tid >> 5;
    const int wm = warp >> 2, wn = warp & 3;
    const int n0 = blockIdx.x * 128, h0 = blockIdx.x * 2;
    const int o0 = blockIdx.y * 128;
    const int bz = blockIdx.z;
    const size_t bb0 = (size_t)bz * PADCELLS;

    const int nA = wn * 32 + (lane & 15);
    const int gA = (nA >> 6) * 66 + (nA & 63);
    const int nB = nA + 16;
    const int gB = (nB >> 6) * 66 + (nB & 63);

    float acc[4][4][4] = {};

    for (int cc = 0; cc < 8; cc++) {
        const int c0 = cc * 64;
        __syncthreads();   // previous chunk fully consumed region + A buffers

        // region load (hi+lo): 264 rows x 64ch
        for (int i = tid; i < 2112; i += 256) {
            int rr = i >> 3, c = i & 7;
            size_t src = (bb0 + h0 * 66 + rr) * 512 + c0 + c * 8;
            cp16(regH + rr * ROWB + c * 16, vt_hi + src);
            cp16(regL + rr * ROWB + c * 16, vt_lo + src);
        }
        // A load li: tap = li/2, hi if even else lo, into buffer li&1
        auto loadA = [&](int li) {
            const int tap = li >> 1;
            const __nv_bfloat16* ap = ((li & 1) ? w_lo : w_hi) + (size_t)tap * 262144;
            const uint32_t buf = aB + (li & 1) * TILE_B;
            #pragma unroll
            for (int i = 0; i < 4; i++) {
                int idx = tid + i * 256;
                int row = idx >> 3, kc = idx & 7;
                cp16(buf + row * ROWB + kc * 16,
                     ap + (size_t)(o0 + row) * 512 + c0 + kc * 8);
            }
            CP_COMMIT();
        };
        loadA(0);   // group 0 = region + A0
        loadA(1);   // group 1 = A1

        for (int li = 0; li < 18; li++) {
            if (li < 17) asm volatile("cp.async.wait_group 1;");
            else         asm volatile("cp.async.wait_group 0;");
            __syncthreads();

            const int tap = li >> 1;
            const int toff = (tap / 3) * 66 + (tap % 3);
            const uint32_t abuf = aB + (li & 1) * TILE_B;
            const uint32_t aoff = abuf + (wm * 64 + (lane & 15)) * ROWB + ((lane >> 4) << 4);

            auto mma_pass = [&](uint32_t reg) {
                const uint32_t boffA = reg + (gA + toff) * ROWB + ((lane >> 4) << 4);
                const uint32_t boffB = reg + (gB + toff) * ROWB + ((lane >> 4) << 4);
                #pragma unroll
                for (int ks = 0; ks < 4; ks++) {
                    uint32_t afr[4][4], bfr[4][2], t4[4];
                    #pragma unroll
                    for (int mi = 0; mi < 4; mi++)
                        LDSM4(afr[mi], aoff + mi * 16 * ROWB + ks * 32);
                    LDSM4(t4, boffA + ks * 32);
                    bfr[0][0] = t4[0]; bfr[0][1] = t4[2]; bfr[1][0] = t4[1]; bfr[1][1] = t4[3];
                    LDSM4(t4, boffB + ks * 32);
                    bfr[2][0] = t4[0]; bfr[2][1] = t4[2]; bfr[3][0] = t4[1]; bfr[3][1] = t4[3];
                    #pragma unroll
                    for (int mi = 0; mi < 4; mi++)
                        #pragma unroll
                        for (int ni = 0; ni < 4; ni++)
                            MMA16816(acc[mi][ni], afr[mi], bfr[ni]);
                }
            };
            if (li & 1) {               // w_lo: one pass over regH
                mma_pass(regH);
            } else {                    // w_hi: regH and regL
                mma_pass(regH);
                mma_pass(regL);
            }
            __syncthreads();
            if (li + 2 < 18) loadA(li + 2);   // overwrite just-consumed buffer
        }
    }

    // BN + SiLU fp32 epilogue
    #pragma unroll
    for (int mi = 0; mi < 4; mi++) {
        const int r0 = o0 + wm * 64 + mi * 16 + (lane >> 2);
        const int r1 = r0 + 8;
        const float sc0 = gg[r0] * rsqrtf(rv[r0] + 1e-5f);
        const float sh0 = bb[r0] - rm[r0] * sc0;
        const float sc1 = gg[r1] * rsqrtf(rv[r1] + 1e-5f);
        const float sh1 = bb[r1] - rm[r1] * sc1;
        float* ob0 = out + ((size_t)bz * 512 + r0) * Nc + n0 + wn * 32 + (lane & 3) * 2;
        float* ob1 = out + ((size_t)bz * 512 + r1) * Nc + n0 + wn * 32 + (lane & 3) * 2;
        #pragma unroll
        for (int ni = 0; ni < 4; ni++) {
            float2 v0, v1;
            v0.x = silu_f(acc[mi][ni][0] * sc0 + sh0);
            v0.y = silu_f(acc[mi][ni][1] * sc0 + sh0);
            v1.x = silu_f(acc[mi][ni][2] * sc1 + sh1);
            v1.y = silu_f(acc[mi][ni][3] * sc1 + sh1);
            *(float2*)(ob0 + ni * 8) = v0;
            *(float2*)(ob1 + ni * 8) = v1;
        }
    }
}

// ---------------------------------------------------------------------------
// HMMA flash attention, warp-local softmax (R7 version: Q fragments from smem).
// S = QhKh + QlKh + QhKl ; O = PhVh + PhVl.
// ---------------------------------------------------------------------------
#define AT_SMEM 110592
__global__ __launch_bounds__(256, 1) void attn_mma(
    const __nv_bfloat16* __restrict__ qh_, const __nv_bfloat16* __restrict__ ql_,
    const __nv_bfloat16* __restrict__ vh_, const __nv_bfloat16* __restrict__ vl_,
    float* __restrict__ ao)
{
    extern __shared__ char smem[];
    const uint32_t sb = smem_u32(smem);
    const uint32_t sQh = sb, sQl = sb + 18432;
    const uint32_t sKV = sb + 36864;
    float* Osf = (float*)(smem + 36864);   // [64][132] overlay after loop

    const int tid = threadIdx.x, lane = tid & 31, warp = tid >> 5;
    const int bh = blockIdx.y;
    const int head = bh & 7, ba = bh >> 3;
    const int b = ba >> 2, area = ba & 3;
    const int q0 = blockIdx.x * 128;
    const int nb = area * 1024;

    const size_t qrow0 = ((size_t)b * 4096 + nb + q0) * 1024 + head * 64;
    const size_t krow0 = ((size_t)b * 4096 + nb) * 1024 + 512 + head * 64;
    const size_t vbase = (size_t)b * PADCELLS * 512 + head * 64;
    const int imrow0 = nb / 64;

    auto loadKV = [&](int t) {
        const uint32_t kb = sKV + (t & 1) * 36864;
        const size_t kr = krow0 + (size_t)(t * 64) * 1024;
        for (int i = tid; i < 512; i += 256) {
            int r = i >> 3, c = i & 7;
            cp16(kb + r * ROWB + c * 16,        qh_ + kr + (size_t)r * 1024 + c * 8);
            cp16(kb + 9216 + r * ROWB + c * 16, ql_ + kr + (size_t)r * 1024 + c * 8);
            size_t vr = vbase + (size_t)((imrow0 + t + 1) * 66 + r + 1) * 512;
            cp16(kb + 18432 + r * ROWB + c * 16, vh_ + vr + c * 8);
            cp16(kb + 27648 + r * ROWB + c * 16, vl_ + vr + c * 8);
        }
        CP_COMMIT();
    };

    for (int i = tid; i < 1024; i += 256) {
        int r = i >> 3, c = i & 7;
        cp16(sQh + r * ROWB + c * 16, qh_ + qrow0 + (size_t)r * 1024 + c * 8);
        cp16(sQl + r * ROWB + c * 16, ql_ + qrow0 + (size_t)r * 1024 + c * 8);
    }
    loadKV(0);   // commit includes Q loads
    loadKV(1);

    float oacc[8][4] = {};
    float mrun0 = -1e30f, mrun1 = -1e30f, lrun0 = 0.0f, lrun1 = 0.0f;

    for (int kt = 0; kt < 16; kt++) {
        if (kt < 15) asm volatile("cp.async.wait_group 1;");
        else         asm volatile("cp.async.wait_group 0;");
        __syncthreads();

        const uint32_t kb = sKV + (kt & 1) * 36864;

        // ---- S (raw scores): 16 q-rows x 64 keys per warp ----
        float sa[8][4] = {};
        #pragma unroll
        for (int ks = 0; ks < 4; ks++) {
            const uint32_t colb = ((lane >> 4) << 4) + ks * 32;
            uint32_t ah[4], al[4], t4[4];
            const uint32_t qoff = (warp * 16 + (lane & 15)) * ROWB + colb;
            LDSM4(ah, sQh + qoff);
            LDSM4(al, sQl + qoff);
            uint32_t bh2[8][2], bl2[8][2];
            #pragma unroll
            for (int nbk = 0; nbk < 4; nbk++) {
                const uint32_t koff = (nbk * 16 + (lane & 15)) * ROWB + colb;
                LDSM4(t4, kb + koff);
                bh2[2*nbk][0] = t4[0]; bh2[2*nbk][1] = t4[2];
                bh2[2*nbk+1][0] = t4[1]; bh2[2*nbk+1][1] = t4[3];
                LDSM4(t4, kb + 9216 + koff);
                bl2[2*nbk][0] = t4[0]; bl2[2*nbk][1] = t4[2];
                bl2[2*nbk+1][0] = t4[1]; bl2[2*nbk+1][1] = t4[3];
            }
            #pragma unroll
            for (int ni = 0; ni < 8; ni++) {
                MMA16816(sa[ni], ah, bh2[ni]);
                MMA16816(sa[ni], al, bh2[ni]);
                MMA16816(sa[ni], ah, bl2[ni]);
            }
        }

        // ---- warp-local online softmax ----
        float m0 = -1e30f, m1 = -1e30f;
        #pragma unroll
        for (int ni = 0; ni < 8; ni++) {
            m0 = fmaxf(m0, fmaxf(sa[ni][0], sa[ni][1]));
            m1 = fmaxf(m1, fmaxf(sa[ni][2], sa[ni][3]));
        }
        m0 = fmaxf(m0, __shfl_xor_sync(0xffffffff, m0, 1));
        m0 = fmaxf(m0, __shfl_xor_sync(0xffffffff, m0, 2));
        m1 = fmaxf(m1, __shfl_xor_sync(0xffffffff, m1, 1));
        m1 = fmaxf(m1, __shfl_xor_sync(0xffffffff, m1, 2));
        const float mn0 = fmaxf(mrun0, m0), mn1 = fmaxf(mrun1, m1);
        const float f0 = exp2f((mrun0 - mn0) * EXPC);
        const float f1 = exp2f((mrun1 - mn1) * EXPC);
        mrun0 = mn0; mrun1 = mn1;

        float s0 = 0.0f, s1 = 0.0f;
        #pragma unroll
        for (int ni = 0; ni < 8; ni++) {
            sa[ni][0] = exp2f((sa[ni][0] - mn0) * EXPC);
            sa[ni][1] = exp2f((sa[ni][1] - mn0) * EXPC);
            sa[ni][2] = exp2f((sa[ni][2] - mn1) * EXPC);
            sa[ni][3] = exp2f((sa[ni][3] - mn1) * EXPC);
            s0 += sa[ni][0] + sa[ni][1];
            s1 += sa[ni][2] + sa[ni][3];
        }
        s0 += __shfl_xor_sync(0xffffffff, s0, 1);
        s0 += __shfl_xor_sync(0xffffffff, s0, 2);
        s1 += __shfl_xor_sync(0xffffffff, s1, 1);
        s1 += __shfl_xor_sync(0xffffffff, s1, 2);
        lrun0 = lrun0 * f0 + s0;
        lrun1 = lrun1 * f1 + s1;
        #pragma unroll
        for (int ni = 0; ni < 8; ni++) {
            oacc[ni][0] *= f0; oacc[ni][1] *= f0;
            oacc[ni][2] *= f1; oacc[ni][3] *= f1;
        }

        // ---- O += Ph*Vh + Ph*Vl ----
        #pragma unroll
        for (int kf = 0; kf < 4; kf++) {
            uint32_t ah[4];
            ah[0] = pack_bf16(sa[2*kf][0],   sa[2*kf][1]);
            ah[1] = pack_bf16(sa[2*kf][2],   sa[2*kf][3]);
            ah[2] = pack_bf16(sa[2*kf+1][0], sa[2*kf+1][1]);
            ah[3] = pack_bf16(sa[2*kf+1][2], sa[2*kf+1][3]);
            uint32_t vh2[8][2], vl2[8][2], t4[4];
            #pragma unroll
            for (int dsp = 0; dsp < 4; dsp++) {
                const uint32_t voff = (kf * 16 + (lane & 15)) * ROWB
                                    + dsp * 32 + ((lane >> 4) << 4);
                LDSM4T(t4, kb + 18432 + voff);
                vh2[dsp*2][0] = t4[0]; vh2[dsp*2][1] = t4[1];
                vh2[dsp*2+1][0] = t4[2]; vh2[dsp*2+1][1] = t4[3];
                LDSM4T(t4, kb + 27648 + voff);
                vl2[dsp*2][0] = t4[0]; vl2[dsp*2][1] = t4[1];
                vl2[dsp*2+1][0] = t4[2]; vl2[dsp*2+1][1] = t4[3];
            }
            #pragma unroll
            for (int ni = 0; ni < 8; ni++) {
                MMA2(oacc[ni], ah, vh2[ni][0], vh2[ni][1]);
                MMA2(oacc[ni], ah, vl2[ni][0], vl2[ni][1]);
            }
        }
        __syncthreads();
        if (kt + 2 < 16) loadKV(kt + 2);
    }
    __syncthreads();

    // ---- normalize in registers, stage [d][q], coalesced store ----
    const float inv0 = 1.0f / lrun0, inv1 = 1.0f / lrun1;
    const int r = warp * 16 + (lane >> 2);
    #pragma unroll
    for (int ni = 0; ni < 8; ni++) {
        int d = ni * 8 + (lane & 3) * 2;
        Osf[d * 132 + r]           = oacc[ni][0] * inv0;
        Osf[(d + 1) * 132 + r]     = oacc[ni][1] * inv0;
        Osf[d * 132 + r + 8]       = oacc[ni][2] * inv1;
        Osf[(d + 1) * 132 + r + 8] = oacc[ni][3] * inv1;
    }
    __syncthreads();
    float* og = ao + ((size_t)b * 512 + head * 64) * Nc + nb + q0;
    for (int i = tid; i < 8192; i += 256) {
        int d = i >> 7, q = i & 127;
        og[(size_t)d * Nc + q] = Osf[d * 132 + q];
    }
}

// ---------------------------------------------------------------------------
extern "C" void kernel_launch(void* const* d_in, const int* in_sizes, int n_in,
                              void* d_out, int out_size)
{
    const float* x     = (const float*)d_in[0];
    const float* qk_w  = (const float*)d_in[1];
    const float* qk_g  = (const float*)d_in[2];
    const float* qk_b  = (const float*)d_in[3];
    const float* qk_rm = (const float*)d_in[4];
    const float* qk_rv = (const float*)d_in[5];
    const float* v_w   = (const float*)d_in[6];
    const float* v_g   = (const float*)d_in[7];
    const float* v_b   = (const float*)d_in[8];
    const float* v_rm  = (const float*)d_in[9];
    const float* v_rv  = (const float*)d_in[10];
    const float* pe_w  = (const float*)d_in[11];
    const float* pe_g  = (const float*)d_in[12];
    const float* pe_b  = (const float*)d_in[13];
    const float* pe_rm = (const float*)d_in[14];
    const float* pe_rv = (const float*)d_in[15];
    const float* pr_w  = (const float*)d_in[16];
    const float* pr_g  = (const float*)d_in[17];
    const float* pr_b  = (const float*)d_in[18];
    const float* pr_rm = (const float*)d_in[19];
    const float* pr_rv = (const float*)d_in[20];

    float *ppb, *aob;
    cudaGetSymbolAddress((void**)&ppb, g_pp);
    cudaGetSymbolAddress((void**)&aob, g_ao);
    __nv_bfloat16 *qkth, *qktl, *xth, *xtl, *vth, *vtl, *sth, *stl;
    __nv_bfloat16 *wqh, *wql, *wvh, *wvl, *wph, *wpl, *weh, *wel;
    cudaGetSymbolAddress((void**)&qkth, g_qkt_hi); cudaGetSymbolAddress((void**)&qktl, g_qkt_lo);
    cudaGetSymbolAddress((void**)&xth, g_xt_hi); cudaGetSymbolAddress((void**)&xtl, g_xt_lo);
    cudaGetSymbolAddress((void**)&vth, g_vt_hi); cudaGetSymbolAddress((void**)&vtl, g_vt_lo);
    cudaGetSymbolAddress((void**)&sth, g_st_hi); cudaGetSymbolAddress((void**)&stl, g_st_lo);
    cudaGetSymbolAddress((void**)&wqh, g_wqk_hi); cudaGetSymbolAddress((void**)&wql, g_wqk_lo);
    cudaGetSymbolAddress((void**)&wvh, g_wv_hi);  cudaGetSymbolAddress((void**)&wvl, g_wv_lo);
    cudaGetSymbolAddress((void**)&wph, g_wpr_hi); cudaGetSymbolAddress((void**)&wpl, g_wpr_lo);
    cudaGetSymbolAddress((void**)&weh, g_wpe_hi); cudaGetSymbolAddress((void**)&wel, g_wpe_lo);

    cudaFuncSetAttribute(mma_gemm, cudaFuncAttributeMaxDynamicSharedMemorySize, SMEM_MMA);
    cudaFuncSetAttribute(conv_mma, cudaFuncAttributeMaxDynamicSharedMemorySize, CV_SMEM);
    cudaFuncSetAttribute(attn_mma, cudaFuncAttributeMaxDynamicSharedMemorySize, AT_SMEM);

    cudaStream_t s0 = 0, s1 = g_ar.s1;

    // ---- s0: x transpose -> qk GEMM -> attn ----
    transpose_split<<<dim3(128, 16, 8), dim3(32, 8), 0, s0>>>(x, nullptr, xth, xtl);
    cudaEventRecord(g_ar.eX, s0);
    split_w<<<2048, 256, 0, s0>>>(qk_w, wqh, wql, 524288);
    mma_gemm<<<dim3(32, 8, 8), 256, SMEM_MMA, s0>>>(wqh, wql, xth, xtl,
        qk_g, qk_b, qk_rm, qk_rv, nullptr, 1024, 2, qkth, qktl);

    // ---- s1: preps -> v GEMM -> conv ----
    reorg_pe<<<9216, 256, 0, s1>>>(pe_w, weh, wel);
    split_w<<<1024, 256, 0, s1>>>(v_w,  wvh, wvl, 262144);
    split_w<<<1024, 256, 0, s1>>>(pr_w, wph, wpl, 262144);
    cudaStreamWaitEvent(s1, g_ar.eX, 0);
    mma_gemm<<<dim3(32, 4, 8), 256, SMEM_MMA, s1>>>(wvh, wvl, xth, xtl,
        v_g, v_b, v_rm, v_rv, nullptr, 512, 3, vth, vtl);
    cudaEventRecord(g_ar.eV, s1);
    conv_mma<<<dim3(32, 4, 8), 256, CV_SMEM, s1>>>(weh, wel, vth, vtl,
        pe_g, pe_b, pe_rm, pe_rv, ppb);
    cudaEventRecord(g_ar.eConv, s1);

    // ---- s0: attention ----
    cudaStreamWaitEvent(s0, g_ar.eV, 0);
    attn_mma<<<dim3(8, 256), 256, AT_SMEM, s0>>>(qkth, qktl, vth, vtl, aob);

    // ---- join, final GEMM ----
    cudaStreamWaitEvent(s0, g_ar.eConv, 0);
    transpose_split<<<dim3(128, 16, 8), dim3(32, 8), 0, s0>>>(aob, ppb, sth, stl);
    mma_gemm<<<dim3(32, 4, 8), 256, SMEM_MMA, s0>>>(wph, wpl, sth, stl,
        pr_g, pr_b, pr_rm, pr_rv, (float*)d_out, 512, 0, nullptr, nullptr);
}

// round 12
// speedup vs baseline: 1.1157x; 1.0688x over previous
#include <cuda_runtime.h>
#include <cuda_bf16.h>
#include <math.h>
#include <stdint.h>

#define Nc 4096
#define PADCELLS 4356   // 66*66 zero-padded image cells (borders stay zero)

__device__ float g_pp[16777216];

__device__ __nv_bfloat16 g_qkt_hi[33554432], g_qkt_lo[33554432]; // [b][n][1024]
__device__ __nv_bfloat16 g_xt_hi[17842176],  g_xt_lo[17842176];  // [b][cell][512]
__device__ __nv_bfloat16 g_vt_hi[17842176],  g_vt_lo[17842176];
__device__ __nv_bfloat16 g_st_hi[17842176],  g_st_lo[17842176];
__device__ __nv_bfloat16 g_wqk_hi[524288],   g_wqk_lo[524288];
__device__ __nv_bfloat16 g_wv_hi [262144],   g_wv_lo [262144];
__device__ __nv_bfloat16 g_wpr_hi[262144],   g_wpr_lo[262144];
__device__ __nv_bfloat16 g_wpe_hi[2359296],  g_wpe_lo[2359296];  // [tap][o][c]

struct AsyncRes {
    cudaStream_t s1;
    cudaEvent_t eX, eConv;
    AsyncRes() {
        cudaStreamCreateWithFlags(&s1, cudaStreamNonBlocking);
        cudaEventCreateWithFlags(&eX, cudaEventDisableTiming);
        cudaEventCreateWithFlags(&eConv, cudaEventDisableTiming);
    }
};
static AsyncRes g_ar;

__device__ __forceinline__ float silu_f(float y) { return y / (1.0f + __expf(-y)); }

__device__ __forceinline__ uint32_t smem_u32(const void* p) {
    uint32_t a;
    asm("{ .reg .u64 t; cvta.to.shared.u64 t, %1; cvt.u32.u64 %0, t; }" : "=r"(a) : "l"(p));
    return a;
}
__device__ __forceinline__ void cp16(uint32_t d, const void* s) {
    asm volatile("cp.async.cg.shared.global [%0], [%1], 16;" :: "r"(d), "l"(s));
}
#define CP_COMMIT() asm volatile("cp.async.commit_group;")
#define LDSM4(r, a) \
    asm volatile("ldmatrix.sync.aligned.m8n8.x4.shared.b16 {%0,%1,%2,%3}, [%4];" \
        : "=r"((r)[0]), "=r"((r)[1]), "=r"((r)[2]), "=r"((r)[3]) : "r"(a))
#define LDSM4T(r, a) \
    asm volatile("ldmatrix.sync.aligned.m8n8.x4.trans.shared.b16 {%0,%1,%2,%3}, [%4];" \
        : "=r"((r)[0]), "=r"((r)[1]), "=r"((r)[2]), "=r"((r)[3]) : "r"(a))
#define MMA16816(d, a, b) \
    asm volatile("mma.sync.aligned.m16n8k16.row.col.f32.bf16.bf16.f32 " \
        "{%0,%1,%2,%3}, {%4,%5,%6,%7}, {%8,%9}, {%0,%1,%2,%3};" \
        : "+f"((d)[0]), "+f"((d)[1]), "+f"((d)[2]), "+f"((d)[3]) \
        : "r"((a)[0]), "r"((a)[1]), "r"((a)[2]), "r"((a)[3]), "r"((b)[0]), "r"((b)[1]))
#define MMA2(d, a, b0, b1) \
    asm volatile("mma.sync.aligned.m16n8k16.row.col.f32.bf16.bf16.f32 " \
        "{%0,%1,%2,%3}, {%4,%5,%6,%7}, {%8,%9}, {%0,%1,%2,%3};" \
        : "+f"((d)[0]), "+f"((d)[1]), "+f"((d)[2]), "+f"((d)[3]) \
        : "r"((a)[0]), "r"((a)[1]), "r"((a)[2]), "r"((a)[3]), "r"(b0), "r"(b1))

__device__ __forceinline__ uint32_t pack_bf16(float lo, float hi) {
    uint32_t r;
    asm("cvt.rn.bf16x2.f32 %0, %1, %2;" : "=r"(r) : "f"(hi), "f"(lo));
    return r;
}

#define ROWB 144
#define TILE_B (128 * ROWB)
#define STAGE_B (2 * TILE_B)
#define SMEM_MMA (2 * STAGE_B)     // 2-stage pipeline: 73,728 B -> 2 CTAs/SM
#define EXPC 0.1803368801f          // 0.125 * log2(e)

// ---------------- prep kernels ----------------
__global__ void split_w(const float* __restrict__ w, __nv_bfloat16* hi, __nv_bfloat16* lo, int n) {
    int i = blockIdx.x * 256 + threadIdx.x;
    if (i < n) {
        float f = w[i];
        __nv_bfloat16 h = __float2bfloat16(f);
        hi[i] = h; lo[i] = __float2bfloat16(f - __bfloat162float(h));
    }
}
__global__ void reorg_pe(const float* __restrict__ pe, __nv_bfloat16* hi, __nv_bfloat16* lo) {
    int i = blockIdx.x * 256 + threadIdx.x;
    if (i < 2359296) {
        int tap = i % 9, c = (i / 9) % 512, o = i / 4608;
        float f = pe[i];
        size_t d = ((size_t)tap * 512 + o) * 512 + c;
        __nv_bfloat16 h = __float2bfloat16(f);
        hi[d] = h; lo[d] = __float2bfloat16(f - __bfloat162float(h));
    }
}
__global__ void transpose_split(const float* __restrict__ X, const float* __restrict__ X2,
                                __nv_bfloat16* __restrict__ hi, __nv_bfloat16* __restrict__ lo)
{
    __shared__ float t[32][33];
    const int tx = threadIdx.x, ty = threadIdx.y;
    const int n0 = blockIdx.x * 32, c0 = blockIdx.y * 32, b = blockIdx.z;
    const float* Xb = X + ((size_t)b * 512 + c0) * Nc + n0;
    const float* X2b = X2 ? (X2 + ((size_t)b * 512 + c0) * Nc + n0) : nullptr;
    for (int i = ty; i < 32; i += 8) {
        float v = Xb[(size_t)i * Nc + tx];
        if (X2b) v += X2b[(size_t)i * Nc + tx];
        t[i][tx] = v;
    }
    __syncthreads();
    for (int i = ty; i < 32; i += 8) {
        float f = t[tx][i];
        int n = n0 + i;
        int cell = ((n >> 6) + 1) * 66 + (n & 63) + 1;
        size_t d = ((size_t)b * PADCELLS + cell) * 512 + c0 + tx;
        __nv_bfloat16 h = __float2bfloat16(f);
        hi[d] = h; lo[d] = __float2bfloat16(f - __bfloat162float(h));
    }
}

// ---------------------------------------------------------------------------
// split-bf16 1x1 GEMM via HMMA, 2-stage cp.async pipeline (2 CTAs/SM).
// mode 0: fp32 [b][O][n]. mode 2: bf16 split [b][n][O]. mode 3: padded image.
// ---------------------------------------------------------------------------
__global__ __launch_bounds__(256, 2) void mma_gemm(
    const __nv_bfloat16* __restrict__ w_hi, const __nv_bfloat16* __restrict__ w_lo,
    const __nv_bfloat16* __restrict__ b_hi, const __nv_bfloat16* __restrict__ b_lo,
    const float* __restrict__ gg, const float* __restrict__ bb,
    const float* __restrict__ rm, const float* __restrict__ rv,
    float* __restrict__ out, int O, int mode,
    __nv_bfloat16* __restrict__ th, __nv_bfloat16* __restrict__ tl)
{
    extern __shared__ char smem[];
    const uint32_t sb = smem_u32(smem);
    const int tid = threadIdx.x;
    const int lane = tid & 31, warp = tid >> 5;
    const int wm = warp >> 2, wn = warp & 3;
    const int n0 = blockIdx.x * 128;
    const int o0 = blockIdx.y * 128;
    const int bz = blockIdx.z;
    const int S = 24;   // 8 c-chunks * 3 split pairs

    auto load_stage = [&](int s) {
        const int c0 = (s / 3) * 64;
        const int p = s % 3;
        const __nv_bfloat16* ap = (p == 1) ? w_lo : w_hi;
        const __nv_bfloat16* bp = (p == 2) ? b_lo : b_hi;
        const uint32_t base = sb + (s & 1) * STAGE_B;
        #pragma unroll
        for (int i = 0; i < 4; i++) {
            int idx = tid + i * 256;
            int row = idx >> 3, kc = idx & 7;
            cp16(base + row * ROWB + kc * 16,
                 ap + (size_t)(o0 + row) * 512 + c0 + kc * 8);
        }
        const size_t bb0 = (size_t)bz * PADCELLS;
        #pragma unroll
        for (int i = 0; i < 4; i++) {
            int idx = tid + i * 256;
            int rn = idx >> 3, kc = idx & 7;
            int nn = n0 + rn;
            int cell = ((nn >> 6) + 1) * 66 + (nn & 63) + 1;
            cp16(base + TILE_B + rn * ROWB + kc * 16,
                 bp + (bb0 + cell) * 512 + c0 + kc * 8);
        }
        CP_COMMIT();
    };

    float acc[4][4][4] = {};

    load_stage(0);
    for (int s = 0; s < S; s++) {
        if (s + 1 < S) { load_stage(s + 1); asm volatile("cp.async.wait_group 1;"); }
        else           { asm volatile("cp.async.wait_group 0;"); }
        __syncthreads();

        const uint32_t base = sb + (s & 1) * STAGE_B;
        const uint32_t aoff = base + (wm * 64 + (lane & 15)) * ROWB + ((lane >> 4) << 4);
        const uint32_t boff = base + TILE_B + (wn * 32 + (lane & 15)) * ROWB + ((lane >> 4) << 4);

        #pragma unroll
        for (int ks = 0; ks < 4; ks++) {
            uint32_t afr[4][4], bfr[4][2], t[4];
            #pragma unroll
            for (int mi = 0; mi < 4; mi++)
                LDSM4(afr[mi], aoff + mi * 16 * ROWB + ks * 32);
            LDSM4(t, boff + ks * 32);
            bfr[0][0] = t[0]; bfr[0][1] = t[2]; bfr[1][0] = t[1]; bfr[1][1] = t[3];
            LDSM4(t, boff + 16 * ROWB + ks * 32);
            bfr[2][0] = t[0]; bfr[2][1] = t[2]; bfr[3][0] = t[1]; bfr[3][1] = t[3];
            #pragma unroll
            for (int mi = 0; mi < 4; mi++)
                #pragma unroll
                for (int ni = 0; ni < 4; ni++)
                    MMA16816(acc[mi][ni], afr[mi], bfr[ni]);
        }
        __syncthreads();
    }

    if (mode == 0) {
        #pragma unroll
        for (int mi = 0; mi < 4; mi++) {
            const int r0 = o0 + wm * 64 + mi * 16 + (lane >> 2);
            const int r1 = r0 + 8;
            const float sc0 = gg[r0] * rsqrtf(rv[r0] + 1e-5f);
            const float sh0 = bb[r0] - rm[r0] * sc0;
            const float sc1 = gg[r1] * rsqrtf(rv[r1] + 1e-5f);
            const float sh1 = bb[r1] - rm[r1] * sc1;
            float* ob0 = out + ((size_t)bz * O + r0) * Nc + n0 + wn * 32 + (lane & 3) * 2;
            float* ob1 = out + ((size_t)bz * O + r1) * Nc + n0 + wn * 32 + (lane & 3) * 2;
            #pragma unroll
            for (int ni = 0; ni < 4; ni++) {
                float2 v0, v1;
                v0.x = silu_f(acc[mi][ni][0] * sc0 + sh0);
                v0.y = silu_f(acc[mi][ni][1] * sc0 + sh0);
                v1.x = silu_f(acc[mi][ni][2] * sc1 + sh1);
                v1.y = silu_f(acc[mi][ni][3] * sc1 + sh1);
                *(float2*)(ob0 + ni * 8) = v0;
                *(float2*)(ob1 + ni * 8) = v1;
            }
        }
    } else {
        __nv_bfloat16* sh = (__nv_bfloat16*)smem;
        __nv_bfloat16* sl = sh + 16384;
        #pragma unroll
        for (int mi = 0; mi < 4; mi++) {
            const int ol0 = wm * 64 + mi * 16 + (lane >> 2);
            const int ol1 = ol0 + 8;
            const int r0 = o0 + ol0, r1 = o0 + ol1;
            const float sc0 = gg[r0] * rsqrtf(rv[r0] + 1e-5f);
            const float sh0 = bb[r0] - rm[r0] * sc0;
            const float sc1 = gg[r1] * rsqrtf(rv[r1] + 1e-5f);
            const float sh1 = bb[r1] - rm[r1] * sc1;
            #pragma unroll
            for (int ni = 0; ni < 4; ni++) {
                const int nl = wn * 32 + ni * 8 + (lane & 3) * 2;
                float v00 = silu_f(acc[mi][ni][0] * sc0 + sh0);
                float v01 = silu_f(acc[mi][ni][1] * sc0 + sh0);
                float v10 = silu_f(acc[mi][ni][2] * sc1 + sh1);
                float v11 = silu_f(acc[mi][ni][3] * sc1 + sh1);
                __nv_bfloat16 h;
                h = __float2bfloat16(v00); sh[nl * 128 + ol0] = h;
                sl[nl * 128 + ol0] = __float2bfloat16(v00 - __bfloat162float(h));
                h = __float2bfloat16(v01); sh[(nl + 1) * 128 + ol0] = h;
                sl[(nl + 1) * 128 + ol0] = __float2bfloat16(v01 - __bfloat162float(h));
                h = __float2bfloat16(v10); sh[nl * 128 + ol1] = h;
                sl[nl * 128 + ol1] = __float2bfloat16(v10 - __bfloat162float(h));
                h = __float2bfloat16(v11); sh[(nl + 1) * 128 + ol1] = h;
                sl[(nl + 1) * 128 + ol1] = __float2bfloat16(v11 - __bfloat162float(h));
            }
        }
        __syncthreads();
        for (int i = tid; i < 2048; i += 256) {
            int n = i >> 4, ch = i & 15;
            uint4 vh4 = *(uint4*)(sh + n * 128 + ch * 8);
            uint4 vl4 = *(uint4*)(sl + n * 128 + ch * 8);
            size_t g;
            if (mode == 2) {
                g = ((size_t)bz * 4096 + n0 + n) * (size_t)O + o0 + ch * 8;
            } else {
                int nn = n0 + n;
                int cell = ((nn >> 6) + 1) * 66 + (nn & 63) + 1;
                g = ((size_t)bz * PADCELLS + cell) * 512 + o0 + ch * 8;
            }
            *(uint4*)(th + g) = vh4;
            *(uint4*)(tl + g) = vl4;
        }
    }
}

// ---------------------------------------------------------------------------
// conv3x3 (R7 original): per c-chunk load haloed region once; 27 uniform
// A-load stages (p0: Wh*regH, p1: Wl*regH, p2: Wh*regL).
// ---------------------------------------------------------------------------
#define CV_REG 38016            // 264 * ROWB
#define CV_A   (2 * CV_REG)     // 76032
#define CV_SMEM (CV_A + 2 * TILE_B)  // 112896
__global__ __launch_bounds__(256, 2) void conv_mma(
    const __nv_bfloat16* __restrict__ w_hi, const __nv_bfloat16* __restrict__ w_lo,
    const __nv_bfloat16* __restrict__ vt_hi, const __nv_bfloat16* __restrict__ vt_lo,
    const float* __restrict__ gg, const float* __restrict__ bb,
    const float* __restrict__ rm, const float* __restrict__ rv,
    float* __restrict__ out)
{
    extern __shared__ char smem[];
    const uint32_t sb = smem_u32(smem);
    const uint32_t regH = sb, regL = sb + CV_REG, aB = sb + CV_A;
    const int tid = threadIdx.x;
    const int lane = tid & 31, warp = tid >> 5;
    const int wm = warp >> 2, wn = warp & 3;
    const int n0 = blockIdx.x * 128, h0 = blockIdx.x * 2;
    const int o0 = blockIdx.y * 128;
    const int bz = blockIdx.z;
    const size_t bb0 = (size_t)bz * PADCELLS;

    const int nA = wn * 32 + (lane & 15);
    const int gA = (nA >> 6) * 66 + (nA & 63);
    const int nB = nA + 16;
    const int gB = (nB >> 6) * 66 + (nB & 63);

    float acc[4][4][4] = {};

    for (int cc = 0; cc < 8; cc++) {
        const int c0 = cc * 64;
        __syncthreads();   // previous chunk fully consumed region + A buffers
        // region load (hi+lo): 264 rows x 64ch
        for (int i = tid; i < 2112; i += 256) {
            int rr = i >> 3, c = i & 7;
            size_t src = (bb0 + h0 * 66 + rr) * 512 + c0 + c * 8;
            cp16(regH + rr * ROWB + c * 16, vt_hi + src);
            cp16(regL + rr * ROWB + c * 16, vt_lo + src);
        }
        auto loadA = [&](int t) {
            const int p = t / 9, tap = t % 9;
            const __nv_bfloat16* ap = ((p == 1) ? w_lo : w_hi) + (size_t)tap * 262144;
            const uint32_t buf = aB + (t & 1) * TILE_B;
            #pragma unroll
            for (int i = 0; i < 4; i++) {
                int idx = tid + i * 256;
                int row = idx >> 3, kc = idx & 7;
                cp16(buf + row * ROWB + kc * 16,
                     ap + (size_t)(o0 + row) * 512 + c0 + kc * 8);
            }
        };
        loadA(0);
        CP_COMMIT();
        for (int t = 0; t < 27; t++) {
            if (t + 1 < 27) { loadA(t + 1); CP_COMMIT(); asm volatile("cp.async.wait_group 1;"); }
            else            { asm volatile("cp.async.wait_group 0;"); }
            __syncthreads();

            const int p = t / 9, tap = t % 9;
            const int toff = (tap / 3) * 66 + (tap % 3);
            const uint32_t reg = (p == 2) ? regL : regH;
            const uint32_t aoff = aB + (t & 1) * TILE_B
                                + (wm * 64 + (lane & 15)) * ROWB + ((lane >> 4) << 4);
            const uint32_t boffA = reg + (gA + toff) * ROWB + ((lane >> 4) << 4);
            const uint32_t boffB = reg + (gB + toff) * ROWB + ((lane >> 4) << 4);

            #pragma unroll
            for (int ks = 0; ks < 4; ks++) {
                uint32_t afr[4][4], bfr[4][2], t4[4];
                #pragma unroll
                for (int mi = 0; mi < 4; mi++)
                    LDSM4(afr[mi], aoff + mi * 16 * ROWB + ks * 32);
                LDSM4(t4, boffA + ks * 32);
                bfr[0][0] = t4[0]; bfr[0][1] = t4[2]; bfr[1][0] = t4[1]; bfr[1][1] = t4[3];
                LDSM4(t4, boffB + ks * 32);
                bfr[2][0] = t4[0]; bfr[2][1] = t4[2]; bfr[3][0] = t4[1]; bfr[3][1] = t4[3];
                #pragma unroll
                for (int mi = 0; mi < 4; mi++)
                    #pragma unroll
                    for (int ni = 0; ni < 4; ni++)
                        MMA16816(acc[mi][ni], afr[mi], bfr[ni]);
            }
            __syncthreads();
        }
    }

    // BN + SiLU fp32 epilogue
    #pragma unroll
    for (int mi = 0; mi < 4; mi++) {
        const int r0 = o0 + wm * 64 + mi * 16 + (lane >> 2);
        const int r1 = r0 + 8;
        const float sc0 = gg[r0] * rsqrtf(rv[r0] + 1e-5f);
        const float sh0 = bb[r0] - rm[r0] * sc0;
        const float sc1 = gg[r1] * rsqrtf(rv[r1] + 1e-5f);
        const float sh1 = bb[r1] - rm[r1] * sc1;
        float* ob0 = out + ((size_t)bz * 512 + r0) * Nc + n0 + wn * 32 + (lane & 3) * 2;
        float* ob1 = out + ((size_t)bz * 512 + r1) * Nc + n0 + wn * 32 + (lane & 3) * 2;
        #pragma unroll
        for (int ni = 0; ni < 4; ni++) {
            float2 v0, v1;
            v0.x = silu_f(acc[mi][ni][0] * sc0 + sh0);
            v0.y = silu_f(acc[mi][ni][1] * sc0 + sh0);
            v1.x = silu_f(acc[mi][ni][2] * sc1 + sh1);
            v1.y = silu_f(acc[mi][ni][3] * sc1 + sh1);
            *(float2*)(ob0 + ni * 8) = v0;
            *(float2*)(ob1 + ni * 8) = v1;
        }
    }
}

// ---------------------------------------------------------------------------
// HMMA flash attention, warp-local softmax.
// S = QhKh + QlKh (K-lo dropped) ; O = PhVh + PhVl.
// Fused epilogue: O/l + pp -> split bf16 -> padded-cell st layout.
// Staging rows are 72 bf16 = 144 B (16B-aligned for uint4 access).
// ---------------------------------------------------------------------------
#define KVSTAGE 27648
#define AT_SMEM (36864 + 2 * KVSTAGE)   // 92,160
__global__ __launch_bounds__(256, 1) void attn_mma(
    const __nv_bfloat16* __restrict__ qh_, const __nv_bfloat16* __restrict__ ql_,
    const __nv_bfloat16* __restrict__ vh_, const __nv_bfloat16* __restrict__ vl_,
    const float* __restrict__ pp,
    __nv_bfloat16* __restrict__ st_hi, __nv_bfloat16* __restrict__ st_lo)
{
    extern __shared__ char smem[];
    const uint32_t sb = smem_u32(smem);
    const uint32_t sQh = sb, sQl = sb + 18432;
    const uint32_t sKV = sb + 36864;
    float* Osf = (float*)(smem + 36864);        // [128][65] fp32 overlay (KV region)
    __nv_bfloat16* stH = (__nv_bfloat16*)smem;  // [128][72] overlay on Q region
    __nv_bfloat16* stL = stH + 128 * 72;        // total 36,864 B = Q region

    const int tid = threadIdx.x, lane = tid & 31, warp = tid >> 5;
    const int bh = blockIdx.y;
    const int head = bh & 7, ba = bh >> 3;
    const int b = ba >> 2, area = ba & 3;
    const int q0 = blockIdx.x * 128;
    const int nb = area * 1024;

    const size_t qrow0 = ((size_t)b * 4096 + nb + q0) * 1024 + head * 64;
    const size_t krow0 = ((size_t)b * 4096 + nb) * 1024 + 512 + head * 64;
    const size_t vbase = (size_t)b * PADCELLS * 512 + head * 64;
    const int imrow0 = nb / 64;

    auto loadKV = [&](int t) {
        const uint32_t kb = sKV + (t & 1) * KVSTAGE;
        const size_t kr = krow0 + (size_t)(t * 64) * 1024;
        for (int i = tid; i < 512; i += 256) {
            int r = i >> 3, c = i & 7;
            cp16(kb + r * ROWB + c * 16, qh_ + kr + (size_t)r * 1024 + c * 8);
            size_t vr = vbase + (size_t)((imrow0 + t + 1) * 66 + r + 1) * 512;
            cp16(kb + 9216 + r * ROWB + c * 16,  vh_ + vr + c * 8);
            cp16(kb + 18432 + r * ROWB + c * 16, vl_ + vr + c * 8);
        }
        CP_COMMIT();
    };

    for (int i = tid; i < 1024; i += 256) {
        int r = i >> 3, c = i & 7;
        cp16(sQh + r * ROWB + c * 16, qh_ + qrow0 + (size_t)r * 1024 + c * 8);
        cp16(sQl + r * ROWB + c * 16, ql_ + qrow0 + (size_t)r * 1024 + c * 8);
    }
    loadKV(0);   // commit includes Q loads
    loadKV(1);

    float oacc[8][4] = {};
    float mrun0 = -1e30f, mrun1 = -1e30f, lrun0 = 0.0f, lrun1 = 0.0f;

    for (int kt = 0; kt < 16; kt++) {
        if (kt < 15) asm volatile("cp.async.wait_group 1;");
        else         asm volatile("cp.async.wait_group 0;");
        __syncthreads();

        const uint32_t kb = sKV + (kt & 1) * KVSTAGE;

        // ---- S: 16 q-rows x 64 keys per warp; S = Qh*Kh + Ql*Kh ----
        float sa[8][4] = {};
        #pragma unroll
        for (int ks = 0; ks < 4; ks++) {
            const uint32_t colb = ((lane >> 4) << 4) + ks * 32;
            uint32_t ah[4], al[4], t4[4];
            const uint32_t qoff = (warp * 16 + (lane & 15)) * ROWB + colb;
            LDSM4(ah, sQh + qoff);
            LDSM4(al, sQl + qoff);
            uint32_t bh2[8][2];
            #pragma unroll
            for (int nbk = 0; nbk < 4; nbk++) {
                const uint32_t koff = (nbk * 16 + (lane & 15)) * ROWB + colb;
                LDSM4(t4, kb + koff);
                bh2[2*nbk][0] = t4[0]; bh2[2*nbk][1] = t4[2];
                bh2[2*nbk+1][0] = t4[1]; bh2[2*nbk+1][1] = t4[3];
            }
            #pragma unroll
            for (int ni = 0; ni < 8; ni++) {
                MMA16816(sa[ni], ah, bh2[ni]);
                MMA16816(sa[ni], al, bh2[ni]);
            }
        }

        // ---- warp-local online softmax ----
        float m0 = -1e30f, m1 = -1e30f;
        #pragma unroll
        for (int ni = 0; ni < 8; ni++) {
            m0 = fmaxf(m0, fmaxf(sa[ni][0], sa[ni][1]));
            m1 = fmaxf(m1, fmaxf(sa[ni][2], sa[ni][3]));
        }
        m0 = fmaxf(m0, __shfl_xor_sync(0xffffffff, m0, 1));
        m0 = fmaxf(m0, __shfl_xor_sync(0xffffffff, m0, 2));
        m1 = fmaxf(m1, __shfl_xor_sync(0xffffffff, m1, 1));
        m1 = fmaxf(m1, __shfl_xor_sync(0xffffffff, m1, 2));
        const float mn0 = fmaxf(mrun0, m0), mn1 = fmaxf(mrun1, m1);
        const float f0 = exp2f((mrun0 - mn0) * EXPC);
        const float f1 = exp2f((mrun1 - mn1) * EXPC);
        mrun0 = mn0; mrun1 = mn1;

        float s0 = 0.0f, s1 = 0.0f;
        #pragma unroll
        for (int ni = 0; ni < 8; ni++) {
            sa[ni][0] = exp2f((sa[ni][0] - mn0) * EXPC);
            sa[ni][1] = exp2f((sa[ni][1] - mn0) * EXPC);
            sa[ni][2] = exp2f((sa[ni][2] - mn1) * EXPC);
            sa[ni][3] = exp2f((sa[ni][3] - mn1) * EXPC);
            s0 += sa[ni][0] + sa[ni][1];
            s1 += sa[ni][2] + sa[ni][3];
        }
        s0 += __shfl_xor_sync(0xffffffff, s0, 1);
        s0 += __shfl_xor_sync(0xffffffff, s0, 2);
        s1 += __shfl_xor_sync(0xffffffff, s1, 1);
        s1 += __shfl_xor_sync(0xffffffff, s1, 2);
        lrun0 = lrun0 * f0 + s0;
        lrun1 = lrun1 * f1 + s1;
        #pragma unroll
        for (int ni = 0; ni < 8; ni++) {
            oacc[ni][0] *= f0; oacc[ni][1] *= f0;
            oacc[ni][2] *= f1; oacc[ni][3] *= f1;
        }

        // ---- O += Ph*Vh + Ph*Vl ----
        #pragma unroll
        for (int kf = 0; kf < 4; kf++) {
            uint32_t ah[4];
            ah[0] = pack_bf16(sa[2*kf][0],   sa[2*kf][1]);
            ah[1] = pack_bf16(sa[2*kf][2],   sa[2*kf][3]);
            ah[2] = pack_bf16(sa[2*kf+1][0], sa[2*kf+1][1]);
            ah[3] = pack_bf16(sa[2*kf+1][2], sa[2*kf+1][3]);
            uint32_t vh2[8][2], vl2[8][2], t4[4];
            #pragma unroll
            for (int dsp = 0; dsp < 4; dsp++) {
                const uint32_t voff = (kf * 16 + (lane & 15)) * ROWB
                                    + dsp * 32 + ((lane >> 4) << 4);
                LDSM4T(t4, kb + 9216 + voff);
                vh2[dsp*2][0] = t4[0]; vh2[dsp*2][1] = t4[1];
                vh2[dsp*2+1][0] = t4[2]; vh2[dsp*2+1][1] = t4[3];
                LDSM4T(t4, kb + 18432 + voff);
                vl2[dsp*2][0] = t4[0]; vl2[dsp*2][1] = t4[1];
                vl2[dsp*2+1][0] = t4[2]; vl2[dsp*2+1][1] = t4[3];
            }
            #pragma unroll
            for (int ni = 0; ni < 8; ni++) {
                MMA2(oacc[ni], ah, vh2[ni][0], vh2[ni][1]);
                MMA2(oacc[ni], ah, vl2[ni][0], vl2[ni][1]);
            }
        }
        __syncthreads();
        if (kt + 2 < 16) loadKV(kt + 2);
    }
    __syncthreads();

    // ---- normalize into Osf [q][65] (fp32, 4B accesses) ----
    const float inv0 = 1.0f / lrun0, inv1 = 1.0f / lrun1;
    const int r = warp * 16 + (lane >> 2);
    #pragma unroll
    for (int ni = 0; ni < 8; ni++) {
        int d = ni * 8 + (lane & 3) * 2;
        Osf[r * 65 + d]           = oacc[ni][0] * inv0;
        Osf[r * 65 + d + 1]       = oacc[ni][1] * inv0;
        Osf[(r + 8) * 65 + d]     = oacc[ni][2] * inv1;
        Osf[(r + 8) * 65 + d + 1] = oacc[ni][3] * inv1;
    }
    __syncthreads();

    // ---- fused epilogue: add pp, split, write padded-cell st layout ----
    const float* ppg = pp + ((size_t)b * 512 + head * 64) * Nc + nb + q0;
    for (int i = tid; i < 8192; i += 256) {
        int ch = i >> 7, q = i & 127;           // q fastest -> pp coalesced
        float v = Osf[q * 65 + ch] + ppg[(size_t)ch * Nc + q];
        __nv_bfloat16 h = __float2bfloat16(v);
        stH[q * 72 + ch] = h;
        stL[q * 72 + ch] = __float2bfloat16(v - __bfloat162float(h));
    }
    __syncthreads();
    for (int i = tid; i < 1024; i += 256) {
        int q = i >> 3, c8 = i & 7;
        int n = nb + q0 + q;
        int cell = ((n >> 6) + 1) * 66 + (n & 63) + 1;
        size_t g = ((size_t)b * PADCELLS + cell) * 512 + head * 64 + c8 * 8;
        *(uint4*)(st_hi + g) = *(uint4*)(stH + q * 72 + c8 * 8);
        *(uint4*)(st_lo + g) = *(uint4*)(stL + q * 72 + c8 * 8);
    }
}

// ---------------------------------------------------------------------------
extern "C" void kernel_launch(void* const* d_in, const int* in_sizes, int n_in,
                              void* d_out, int out_size)
{
    const float* x     = (const float*)d_in[0];
    const float* qk_w  = (const float*)d_in[1];
    const float* qk_g  = (const float*)d_in[2];
    const float* qk_b  = (const float*)d_in[3];
    const float* qk_rm = (const float*)d_in[4];
    const float* qk_rv = (const float*)d_in[5];
    const float* v_w   = (const float*)d_in[6];
    const float* v_g   = (const float*)d_in[7];
    const float* v_b   = (const float*)d_in[8];
    const float* v_rm  = (const float*)d_in[9];
    const float* v_rv  = (const float*)d_in[10];
    const float* pe_w  = (const float*)d_in[11];
    const float* pe_g  = (const float*)d_in[12];
    const float* pe_b  = (const float*)d_in[13];
    const float* pe_rm = (const float*)d_in[14];
    const float* pe_rv = (const float*)d_in[15];
    const float* pr_w  = (const float*)d_in[16];
    const float* pr_g  = (const float*)d_in[17];
    const float* pr_b  = (const float*)d_in[18];
    const float* pr_rm = (const float*)d_in[19];
    const float* pr_rv = (const float*)d_in[20];

    float* ppb;
    cudaGetSymbolAddress((void**)&ppb, g_pp);
    __nv_bfloat16 *qkth, *qktl, *xth, *xtl, *vth, *vtl, *sth, *stl;
    __nv_bfloat16 *wqh, *wql, *wvh, *wvl, *wph, *wpl, *weh, *wel;
    cudaGetSymbolAddress((void**)&qkth, g_qkt_hi); cudaGetSymbolAddress((void**)&qktl, g_qkt_lo);
    cudaGetSymbolAddress((void**)&xth, g_xt_hi); cudaGetSymbolAddress((void**)&xtl, g_xt_lo);
    cudaGetSymbolAddress((void**)&vth, g_vt_hi); cudaGetSymbolAddress((void**)&vtl, g_vt_lo);
    cudaGetSymbolAddress((void**)&sth, g_st_hi); cudaGetSymbolAddress((void**)&stl, g_st_lo);
    cudaGetSymbolAddress((void**)&wqh, g_wqk_hi); cudaGetSymbolAddress((void**)&wql, g_wqk_lo);
    cudaGetSymbolAddress((void**)&wvh, g_wv_hi);  cudaGetSymbolAddress((void**)&wvl, g_wv_lo);
    cudaGetSymbolAddress((void**)&wph, g_wpr_hi); cudaGetSymbolAddress((void**)&wpl, g_wpr_lo);
    cudaGetSymbolAddress((void**)&weh, g_wpe_hi); cudaGetSymbolAddress((void**)&wel, g_wpe_lo);

    cudaFuncSetAttribute(mma_gemm, cudaFuncAttributeMaxDynamicSharedMemorySize, SMEM_MMA);
    cudaFuncSetAttribute(conv_mma, cudaFuncAttributeMaxDynamicSharedMemorySize, CV_SMEM);
    cudaFuncSetAttribute(attn_mma, cudaFuncAttributeMaxDynamicSharedMemorySize, AT_SMEM);

    cudaStream_t s0 = 0, s1 = g_ar.s1;

    // ---- s0: x transpose -> qk GEMM ----
    transpose_split<<<dim3(128, 16, 8), dim3(32, 8), 0, s0>>>(x, nullptr, xth, xtl);
    cudaEventRecord(g_ar.eX, s0);
    split_w<<<2048, 256, 0, s0>>>(qk_w, wqh, wql, 524288);
    mma_gemm<<<dim3(32, 8, 8), 256, SMEM_MMA, s0>>>(wqh, wql, xth, xtl,
        qk_g, qk_b, qk_rm, qk_rv, nullptr, 1024, 2, qkth, qktl);

    // ---- s1: preps -> v GEMM -> conv ----
    reorg_pe<<<9216, 256, 0, s1>>>(pe_w, weh, wel);
    split_w<<<1024, 256, 0, s1>>>(v_w,  wvh, wvl, 262144);
    split_w<<<1024, 256, 0, s1>>>(pr_w, wph, wpl, 262144);
    cudaStreamWaitEvent(s1, g_ar.eX, 0);
    mma_gemm<<<dim3(32, 4, 8), 256, SMEM_MMA, s1>>>(wvh, wvl, xth, xtl,
        v_g, v_b, v_rm, v_rv, nullptr, 512, 3, vth, vtl);
    conv_mma<<<dim3(32, 4, 8), 256, CV_SMEM, s1>>>(weh, wel, vth, vtl,
        pe_g, pe_b, pe_rm, pe_rv, ppb);
    cudaEventRecord(g_ar.eConv, s1);

    // ---- s0: attention (consumes qk, v, pp; emits st) -> final GEMM ----
    cudaStreamWaitEvent(s0, g_ar.eConv, 0);
    attn_mma<<<dim3(8, 256), 256, AT_SMEM, s0>>>(qkth, qktl, vth, vtl,
        ppb, sth, stl);
    mma_gemm<<<dim3(32, 4, 8), 256, SMEM_MMA, s0>>>(wph, wpl, sth, stl,
        pr_g, pr_b, pr_rm, pr_rv, (float*)d_out, 512, 0, nullptr, nullptr);
}